// round 2
// baseline (speedup 1.0000x reference)
#include <cuda_runtime.h>

// Problem constants (fixed by dataset)
#define BB 64
#define TT 128
#define SS 512
#define EE 1024
#define DD 512
#define NEGINF (-1.0e10f)

// Scratch (allocation-free rule: device globals)
__device__ float g_proj[(size_t)BB * SS * DD];   // [B,S,D]  67 MB
__device__ float g_wc[(size_t)BB * TT * EE];     // [B,T,E]  33.5 MB
__device__ float g_attn_scratch[(size_t)BB * TT * SS];
__device__ float g_me_scratch[(size_t)BB * TT * SS];

// ---------------------------------------------------------------------------
// Tiled GEMM building blocks: BM=BN=64, BK=16, 256 threads, 4x4 per thread.
// A tiles are stored k-major (transposed) in SMEM with pad 65 to kill
// store-bank conflicts; B tiles stored n-major.
// ---------------------------------------------------------------------------

// Kernel 1: proj[m,n] = (sum_k enc[m,k]*W[k,n] + bias[n]) * maskf[m]
// m = b*S+s over 32768, K=1024, N=512
__global__ __launch_bounds__(256)
void k_proj(const float* __restrict__ enc, const float* __restrict__ W,
            const float* __restrict__ bias, const int* __restrict__ mask)
{
    __shared__ float As[16][65];
    __shared__ float Bs[16][64];
    const int bm = blockIdx.y * 64;
    const int bn = blockIdx.x * 64;
    const int tid = threadIdx.x;
    const int tx = tid & 15, ty = tid >> 4;
    const int arow = tid >> 2, acol = (tid & 3) * 4;
    const int brow = tid >> 4, bcol = (tid & 15) * 4;

    float acc[4][4] = {};
    for (int k0 = 0; k0 < EE; k0 += 16) {
        float4 av = *(const float4*)&enc[(size_t)(bm + arow) * EE + k0 + acol];
        As[acol + 0][arow] = av.x;
        As[acol + 1][arow] = av.y;
        As[acol + 2][arow] = av.z;
        As[acol + 3][arow] = av.w;
        *(float4*)&Bs[brow][bcol] =
            *(const float4*)&W[(size_t)(k0 + brow) * DD + bn + bcol];
        __syncthreads();
#pragma unroll
        for (int kk = 0; kk < 16; kk++) {
            float a[4], b[4];
#pragma unroll
            for (int i = 0; i < 4; i++) a[i] = As[kk][ty * 4 + i];
#pragma unroll
            for (int j = 0; j < 4; j++) b[j] = Bs[kk][tx * 4 + j];
#pragma unroll
            for (int i = 0; i < 4; i++)
#pragma unroll
                for (int j = 0; j < 4; j++) acc[i][j] += a[i] * b[j];
        }
        __syncthreads();
    }
#pragma unroll
    for (int i = 0; i < 4; i++) {
        int m = bm + ty * 4 + i;
        float mf = (float)mask[m];
#pragma unroll
        for (int j = 0; j < 4; j++) {
            int n = bn + tx * 4 + j;
            g_proj[(size_t)m * DD + n] = (acc[i][j] + bias[n]) * mf;
        }
    }
}

// Kernel 2 (per batch): me[b,t,s] = sum_d dec[b,t,d]*proj[b,s,d] + NEGINF*(1-maskf[b,s])
__global__ __launch_bounds__(256)
void k_energy(const float* __restrict__ dec, const int* __restrict__ mask,
              float* __restrict__ me)
{
    const int b = blockIdx.z;
    const float* A = dec + (size_t)b * TT * DD;      // [T, D]
    const float* Bp = g_proj + (size_t)b * SS * DD;  // [S, D]
    __shared__ float As[16][65];
    __shared__ float Bs[16][65];
    const int bm = blockIdx.y * 64;   // t
    const int bn = blockIdx.x * 64;   // s
    const int tid = threadIdx.x;
    const int tx = tid & 15, ty = tid >> 4;
    const int row = tid >> 2, col = (tid & 3) * 4;

    float acc[4][4] = {};
    for (int k0 = 0; k0 < DD; k0 += 16) {
        float4 av = *(const float4*)&A[(size_t)(bm + row) * DD + k0 + col];
        As[col + 0][row] = av.x; As[col + 1][row] = av.y;
        As[col + 2][row] = av.z; As[col + 3][row] = av.w;
        float4 bv = *(const float4*)&Bp[(size_t)(bn + row) * DD + k0 + col];
        Bs[col + 0][row] = bv.x; Bs[col + 1][row] = bv.y;
        Bs[col + 2][row] = bv.z; Bs[col + 3][row] = bv.w;
        __syncthreads();
#pragma unroll
        for (int kk = 0; kk < 16; kk++) {
            float a[4], bb[4];
#pragma unroll
            for (int i = 0; i < 4; i++) a[i] = As[kk][ty * 4 + i];
#pragma unroll
            for (int j = 0; j < 4; j++) bb[j] = Bs[kk][tx * 4 + j];
#pragma unroll
            for (int i = 0; i < 4; i++)
#pragma unroll
                for (int j = 0; j < 4; j++) acc[i][j] += a[i] * bb[j];
        }
        __syncthreads();
    }
#pragma unroll
    for (int i = 0; i < 4; i++) {
        int t = bm + ty * 4 + i;
#pragma unroll
        for (int j = 0; j < 4; j++) {
            int s = bn + tx * 4 + j;
            float neg = mask[(size_t)b * SS + s] ? 0.0f : NEGINF;
            me[((size_t)b * TT + t) * SS + s] = acc[i][j] + neg;
        }
    }
}

// Kernel 3: row softmax over S=512, one block (256 thr) per (b,t) row.
__global__ __launch_bounds__(256)
void k_softmax(const float* __restrict__ me, float* __restrict__ attn)
{
    const int row = blockIdx.x;
    const float* x = me + (size_t)row * SS;
    float* y = attn + (size_t)row * SS;
    const int tid = threadIdx.x;
    __shared__ float smax[8];
    __shared__ float ssum[8];

    float v0 = x[tid], v1 = x[tid + 256];
    float m = fmaxf(v0, v1);
#pragma unroll
    for (int o = 16; o; o >>= 1) m = fmaxf(m, __shfl_xor_sync(0xffffffffu, m, o));
    if ((tid & 31) == 0) smax[tid >> 5] = m;
    __syncthreads();
    float M = smax[0];
#pragma unroll
    for (int i = 1; i < 8; i++) M = fmaxf(M, smax[i]);

    float e0 = __expf(v0 - M), e1 = __expf(v1 - M);
    float s = e0 + e1;
#pragma unroll
    for (int o = 16; o; o >>= 1) s += __shfl_xor_sync(0xffffffffu, s, o);
    if ((tid & 31) == 0) ssum[tid >> 5] = s;
    __syncthreads();
    float S = 0.0f;
#pragma unroll
    for (int i = 0; i < 8; i++) S += ssum[i];
    float inv = 1.0f / S;
    y[tid] = e0 * inv;
    y[tid + 256] = e1 * inv;
}

// Kernel 4 (per batch): wc[b,t,e] = sum_s attn[b,t,s]*enc[b,s,e]
__global__ __launch_bounds__(256)
void k_wc(const float* __restrict__ attn, const float* __restrict__ enc)
{
    const int b = blockIdx.z;
    const float* A = attn + (size_t)b * TT * SS;   // [T, S]
    const float* Bp = enc + (size_t)b * SS * EE;   // [S, E]
    __shared__ float As[16][65];
    __shared__ float Bs[16][64];
    const int bm = blockIdx.y * 64;  // t
    const int bn = blockIdx.x * 64;  // e
    const int tid = threadIdx.x;
    const int tx = tid & 15, ty = tid >> 4;
    const int arow = tid >> 2, acol = (tid & 3) * 4;
    const int brow = tid >> 4, bcol = (tid & 15) * 4;

    float acc[4][4] = {};
    for (int k0 = 0; k0 < SS; k0 += 16) {
        float4 av = *(const float4*)&A[(size_t)(bm + arow) * SS + k0 + acol];
        As[acol + 0][arow] = av.x; As[acol + 1][arow] = av.y;
        As[acol + 2][arow] = av.z; As[acol + 3][arow] = av.w;
        *(float4*)&Bs[brow][bcol] =
            *(const float4*)&Bp[(size_t)(k0 + brow) * EE + bn + bcol];
        __syncthreads();
#pragma unroll
        for (int kk = 0; kk < 16; kk++) {
            float a[4], bb[4];
#pragma unroll
            for (int i = 0; i < 4; i++) a[i] = As[kk][ty * 4 + i];
#pragma unroll
            for (int j = 0; j < 4; j++) bb[j] = Bs[kk][tx * 4 + j];
#pragma unroll
            for (int i = 0; i < 4; i++)
#pragma unroll
                for (int j = 0; j < 4; j++) acc[i][j] += a[i] * bb[j];
        }
        __syncthreads();
    }
#pragma unroll
    for (int i = 0; i < 4; i++) {
        int t = bm + ty * 4 + i;
#pragma unroll
        for (int j = 0; j < 4; j++) {
            int e = bn + tx * 4 + j;
            g_wc[((size_t)b * TT + t) * EE + e] = acc[i][j];
        }
    }
}

// Kernel 5: h_tilde[m,n] = tanh( sum_{k<1024} wc[m,k]*W_out[k,n]
//                              + sum_{k>=1024} dec[m,k-1024]*W_out[k,n] )
// m over B*T = 8192, K=1536, N=512
__global__ __launch_bounds__(256)
void k_out(const float* __restrict__ dec, const float* __restrict__ Wout,
           float* __restrict__ ht)
{
    __shared__ float As[16][65];
    __shared__ float Bs[16][64];
    const int bm = blockIdx.y * 64;
    const int bn = blockIdx.x * 64;
    const int tid = threadIdx.x;
    const int tx = tid & 15, ty = tid >> 4;
    const int arow = tid >> 2, acol = (tid & 3) * 4;
    const int brow = tid >> 4, bcol = (tid & 15) * 4;

    float acc[4][4] = {};
    for (int k0 = 0; k0 < EE + DD; k0 += 16) {
        float4 av;
        if (k0 < EE)
            av = *(const float4*)&g_wc[(size_t)(bm + arow) * EE + k0 + acol];
        else
            av = *(const float4*)&dec[(size_t)(bm + arow) * DD + (k0 - EE) + acol];
        As[acol + 0][arow] = av.x; As[acol + 1][arow] = av.y;
        As[acol + 2][arow] = av.z; As[acol + 3][arow] = av.w;
        *(float4*)&Bs[brow][bcol] =
            *(const float4*)&Wout[(size_t)(k0 + brow) * DD + bn + bcol];
        __syncthreads();
#pragma unroll
        for (int kk = 0; kk < 16; kk++) {
            float a[4], bb[4];
#pragma unroll
            for (int i = 0; i < 4; i++) a[i] = As[kk][ty * 4 + i];
#pragma unroll
            for (int j = 0; j < 4; j++) bb[j] = Bs[kk][tx * 4 + j];
#pragma unroll
            for (int i = 0; i < 4; i++)
#pragma unroll
                for (int j = 0; j < 4; j++) acc[i][j] += a[i] * bb[j];
        }
        __syncthreads();
    }
#pragma unroll
    for (int i = 0; i < 4; i++) {
        int m = bm + ty * 4 + i;
#pragma unroll
        for (int j = 0; j < 4; j++) {
            int n = bn + tx * 4 + j;
            ht[(size_t)m * DD + n] = tanhf(acc[i][j]);
        }
    }
}

extern "C" void kernel_launch(void* const* d_in, const int* in_sizes, int n_in,
                              void* d_out, int out_size)
{
    const float* dec    = (const float*)d_in[0];  // [B,T,DEC]
    const float* enc    = (const float*)d_in[1];  // [B,S,ENC]
    const int*   mask   = (const int*)d_in[2];    // [B,S]
    const float* W_attn = (const float*)d_in[3];  // [ENC,DEC]
    const float* b_attn = (const float*)d_in[4];  // [DEC]
    const float* W_out  = (const float*)d_in[5];  // [ENC+DEC,DEC]
    float* out = (float*)d_out;

    const size_t n_h    = (size_t)BB * TT * DD;
    const size_t n_attn = (size_t)BB * TT * SS;
    const size_t n_me   = (size_t)BB * TT * SS;

    float* h_tilde = out;
    float* attn;
    float* me;
    if ((size_t)out_size >= n_h + n_attn + n_me) {
        attn = out + n_h;
        me   = out + n_h + n_attn;
    } else {
        // Defensive fallback: only h_tilde fits in d_out; keep the
        // intermediates in device-global scratch.
        void* p;
        cudaGetSymbolAddress(&p, g_attn_scratch); attn = (float*)p;
        cudaGetSymbolAddress(&p, g_me_scratch);   me = (float*)p;
    }

    // 1. proj = (enc @ W_attn + b) * mask     M=32768 K=1024 N=512
    k_proj<<<dim3(DD / 64, (BB * SS) / 64), 256>>>(enc, W_attn, b_attn, mask);
    // 2. masked energies                       per-batch M=128 N=512 K=512
    k_energy<<<dim3(SS / 64, TT / 64, BB), 256>>>(dec, mask, me);
    // 3. softmax rows
    k_softmax<<<dim3(BB * TT), 256>>>(me, attn);
    // 4. weighted context                      per-batch M=128 N=1024 K=512
    k_wc<<<dim3(EE / 64, TT / 64, BB), 256>>>(attn, enc);
    // 5. h_tilde = tanh([wc, dec] @ W_out)     M=8192 K=1536 N=512
    k_out<<<dim3(DD / 64, (BB * TT) / 64), 256>>>(dec, W_out, h_tilde);
}

// round 3
// speedup vs baseline: 1.8107x; 1.8107x over previous
#include <cuda_runtime.h>

// Problem constants (fixed by dataset)
#define BB 64
#define TT 128
#define SS 512
#define EE 1024
#define DD 512
#define NEGINF (-1.0e10f)

// Scratch (allocation-free rule: device globals)
__device__ float g_P[(size_t)BB * TT * EE];    // P = dec @ W_attn^T  [B*T, E] 33.5 MB
__device__ float g_wc[(size_t)BB * TT * EE];   // weighted context    [B*T, E] 33.5 MB
__device__ float g_c[(size_t)BB * TT];         // c = dec . b_attn    [B*T]
__device__ float g_attn_scratch[(size_t)BB * TT * SS];
__device__ float g_me_scratch[(size_t)BB * TT * SS];

// ---------------------------------------------------------------------------
// GEMM pattern: BM=BN=128, BK=16, 256 threads, 8x8 micro-tile,
// double-buffered SMEM + register prefetch. SMEM rows padded to 132 floats.
// A stored k-major (transposed) in SMEM; B stored [k][n].
// ---------------------------------------------------------------------------

#define GEMM_COMPUTE(cur)                                                     \
    _Pragma("unroll")                                                         \
    for (int kk = 0; kk < 16; ++kk) {                                         \
        float a[8], b[8];                                                     \
        *(float4*)&a[0] = *(const float4*)&As[cur][kk][ty * 8];               \
        *(float4*)&a[4] = *(const float4*)&As[cur][kk][ty * 8 + 4];           \
        *(float4*)&b[0] = *(const float4*)&Bs[cur][kk][tx * 8];               \
        *(float4*)&b[4] = *(const float4*)&Bs[cur][kk][tx * 8 + 4];           \
        _Pragma("unroll")                                                     \
        for (int i = 0; i < 8; i++)                                           \
            _Pragma("unroll")                                                 \
            for (int j = 0; j < 8; j++) acc[i][j] += a[i] * b[j];             \
    }

#define STORE_T(dstbuf, v, p)                                                 \
    dstbuf[lcol + 0][lrow + (p)*64] = (v).x;                                  \
    dstbuf[lcol + 1][lrow + (p)*64] = (v).y;                                  \
    dstbuf[lcol + 2][lrow + (p)*64] = (v).z;                                  \
    dstbuf[lcol + 3][lrow + (p)*64] = (v).w;

// Kernel c: c[m] = sum_d dec[m,d] * b_attn[d]
__global__ __launch_bounds__(256)
void k_c(const float* __restrict__ dec, const float* __restrict__ ba)
{
    const int m = blockIdx.x * 8 + (threadIdx.x >> 5);
    const int lane = threadIdx.x & 31;
    float s = 0.0f;
#pragma unroll
    for (int it = 0; it < 4; it++) {
        float4 v = *(const float4*)&dec[(size_t)m * DD + it * 128 + lane * 4];
        float4 w = *(const float4*)&ba[it * 128 + lane * 4];
        s += v.x * w.x + v.y * w.y + v.z * w.z + v.w * w.w;
    }
#pragma unroll
    for (int o = 16; o; o >>= 1) s += __shfl_xor_sync(0xffffffffu, s, o);
    if (lane == 0) g_c[m] = s;
}

// Kernel P: P[m,e] = sum_d dec[m,d] * W_attn[e,d]   M=8192, N=1024, K=512
// Both A (dec, row-major [m,k]) and B (W, row-major [n,k]) load transposed-style.
__global__ __launch_bounds__(256)
void k_P(const float* __restrict__ dec, const float* __restrict__ W)
{
    __shared__ float As[2][16][132];
    __shared__ float Bs[2][16][132];
    const int bm = blockIdx.y * 128;
    const int bn = blockIdx.x * 128;
    const int tid = threadIdx.x;
    const int tx = tid & 15, ty = tid >> 4;
    const int lrow = tid >> 2, lcol = (tid & 3) * 4;

#pragma unroll
    for (int p = 0; p < 2; p++) {
        float4 va = *(const float4*)&dec[(size_t)(bm + lrow + p * 64) * DD + lcol];
        STORE_T(As[0], va, p);
        float4 vb = *(const float4*)&W[(size_t)(bn + lrow + p * 64) * DD + lcol];
        STORE_T(Bs[0], vb, p);
    }
    __syncthreads();

    float acc[8][8] = {};
    const int nt = DD / 16;
    for (int t = 0; t < nt; ++t) {
        const int cur = t & 1, nxt = cur ^ 1;
        float4 pa[2], pb[2];
        if (t + 1 < nt) {
            const int k0 = (t + 1) * 16;
#pragma unroll
            for (int p = 0; p < 2; p++) {
                pa[p] = *(const float4*)&dec[(size_t)(bm + lrow + p * 64) * DD + k0 + lcol];
                pb[p] = *(const float4*)&W[(size_t)(bn + lrow + p * 64) * DD + k0 + lcol];
            }
        }
        GEMM_COMPUTE(cur)
        if (t + 1 < nt) {
#pragma unroll
            for (int p = 0; p < 2; p++) {
                STORE_T(As[nxt], pa[p], p);
                STORE_T(Bs[nxt], pb[p], p);
            }
        }
        __syncthreads();
    }
#pragma unroll
    for (int i = 0; i < 8; i++) {
        const size_t m = bm + ty * 8 + i;
        *(float4*)&g_P[m * EE + bn + tx * 8]     = *(float4*)&acc[i][0];
        *(float4*)&g_P[m * EE + bn + tx * 8 + 4] = *(float4*)&acc[i][4];
    }
}

// Kernel energy (per batch): me[t,s] = mask ? P[t,:].enc[s,:] + c[t] : NEGINF
// M=T=128 (bm=0), N=S=512, K=E=1024.  B transposed from enc[b] (row-major [s,e]).
__global__ __launch_bounds__(256)
void k_energy(const float* __restrict__ enc, const int* __restrict__ mask,
              float* __restrict__ me)
{
    __shared__ float As[2][16][132];
    __shared__ float Bs[2][16][132];
    const int b = blockIdx.z;
    const float* A = g_P + (size_t)b * TT * EE;
    const float* Ep = enc + (size_t)b * SS * EE;
    const int bn = blockIdx.x * 128;
    const int tid = threadIdx.x;
    const int tx = tid & 15, ty = tid >> 4;
    const int lrow = tid >> 2, lcol = (tid & 3) * 4;

#pragma unroll
    for (int p = 0; p < 2; p++) {
        float4 va = *(const float4*)&A[(size_t)(lrow + p * 64) * EE + lcol];
        STORE_T(As[0], va, p);
        float4 vb = *(const float4*)&Ep[(size_t)(bn + lrow + p * 64) * EE + lcol];
        STORE_T(Bs[0], vb, p);
    }
    __syncthreads();

    float acc[8][8] = {};
    const int nt = EE / 16;
    for (int t = 0; t < nt; ++t) {
        const int cur = t & 1, nxt = cur ^ 1;
        float4 pa[2], pb[2];
        if (t + 1 < nt) {
            const int k0 = (t + 1) * 16;
#pragma unroll
            for (int p = 0; p < 2; p++) {
                pa[p] = *(const float4*)&A[(size_t)(lrow + p * 64) * EE + k0 + lcol];
                pb[p] = *(const float4*)&Ep[(size_t)(bn + lrow + p * 64) * EE + k0 + lcol];
            }
        }
        GEMM_COMPUTE(cur)
        if (t + 1 < nt) {
#pragma unroll
            for (int p = 0; p < 2; p++) {
                STORE_T(As[nxt], pa[p], p);
                STORE_T(Bs[nxt], pb[p], p);
            }
        }
        __syncthreads();
    }
#pragma unroll
    for (int i = 0; i < 8; i++) {
        const int t = ty * 8 + i;
        const float ct = g_c[(size_t)b * TT + t];
#pragma unroll
        for (int j = 0; j < 8; j++) {
            const int s = bn + tx * 8 + j;
            me[((size_t)b * TT + t) * SS + s] =
                mask[(size_t)b * SS + s] ? (acc[i][j] + ct) : NEGINF;
        }
    }
}

// Kernel 3: row softmax over S=512, one block (256 thr) per (b,t) row.
__global__ __launch_bounds__(256)
void k_softmax(const float* __restrict__ me, float* __restrict__ attn)
{
    const int row = blockIdx.x;
    const float* x = me + (size_t)row * SS;
    float* y = attn + (size_t)row * SS;
    const int tid = threadIdx.x;
    __shared__ float smax[8];
    __shared__ float ssum[8];

    float v0 = x[tid], v1 = x[tid + 256];
    float m = fmaxf(v0, v1);
#pragma unroll
    for (int o = 16; o; o >>= 1) m = fmaxf(m, __shfl_xor_sync(0xffffffffu, m, o));
    if ((tid & 31) == 0) smax[tid >> 5] = m;
    __syncthreads();
    float M = smax[0];
#pragma unroll
    for (int i = 1; i < 8; i++) M = fmaxf(M, smax[i]);

    float e0 = __expf(v0 - M), e1 = __expf(v1 - M);
    float s = e0 + e1;
#pragma unroll
    for (int o = 16; o; o >>= 1) s += __shfl_xor_sync(0xffffffffu, s, o);
    if ((tid & 31) == 0) ssum[tid >> 5] = s;
    __syncthreads();
    float S = 0.0f;
#pragma unroll
    for (int i = 0; i < 8; i++) S += ssum[i];
    float inv = 1.0f / S;
    y[tid] = e0 * inv;
    y[tid + 256] = e1 * inv;
}

// Kernel wc (per batch): wc[t,e] = sum_s attn[t,s]*enc[s,e]
// M=T=128 (bm=0), N=E=1024, K=S=512. B direct row-major [k=s][n=e].
__global__ __launch_bounds__(256)
void k_wc(const float* __restrict__ attn, const float* __restrict__ enc)
{
    __shared__ float As[2][16][132];
    __shared__ float Bs[2][16][132];
    const int b = blockIdx.z;
    const float* A = attn + (size_t)b * TT * SS;
    const float* Ep = enc + (size_t)b * SS * EE;
    const int bn = blockIdx.x * 128;
    const int tid = threadIdx.x;
    const int tx = tid & 15, ty = tid >> 4;
    const int lrow = tid >> 2, lcol = (tid & 3) * 4;
    const int krow = tid >> 5, ncol = (tid & 31) * 4;

#pragma unroll
    for (int p = 0; p < 2; p++) {
        float4 va = *(const float4*)&A[(size_t)(lrow + p * 64) * SS + lcol];
        STORE_T(As[0], va, p);
        float4 vb = *(const float4*)&Ep[(size_t)(krow + p * 8) * EE + bn + ncol];
        *(float4*)&Bs[0][krow + p * 8][ncol] = vb;
    }
    __syncthreads();

    float acc[8][8] = {};
    const int nt = SS / 16;
    for (int t = 0; t < nt; ++t) {
        const int cur = t & 1, nxt = cur ^ 1;
        float4 pa[2], pb[2];
        if (t + 1 < nt) {
            const int k0 = (t + 1) * 16;
#pragma unroll
            for (int p = 0; p < 2; p++) {
                pa[p] = *(const float4*)&A[(size_t)(lrow + p * 64) * SS + k0 + lcol];
                pb[p] = *(const float4*)&Ep[(size_t)(k0 + krow + p * 8) * EE + bn + ncol];
            }
        }
        GEMM_COMPUTE(cur)
        if (t + 1 < nt) {
#pragma unroll
            for (int p = 0; p < 2; p++) {
                STORE_T(As[nxt], pa[p], p);
                *(float4*)&Bs[nxt][krow + p * 8][ncol] = pb[p];
            }
        }
        __syncthreads();
    }
#pragma unroll
    for (int i = 0; i < 8; i++) {
        const size_t m = (size_t)b * TT + ty * 8 + i;
        *(float4*)&g_wc[m * EE + bn + tx * 8]     = *(float4*)&acc[i][0];
        *(float4*)&g_wc[m * EE + bn + tx * 8 + 4] = *(float4*)&acc[i][4];
    }
}

// Kernel out: ht[m,n] = tanh( [wc | dec][m,:] @ W_out[:,n] )
// M=8192, K=1536 (1024 from wc, 512 from dec), N=512. B direct row-major.
__global__ __launch_bounds__(256)
void k_out(const float* __restrict__ dec, const float* __restrict__ Wout,
           float* __restrict__ ht)
{
    __shared__ float As[2][16][132];
    __shared__ float Bs[2][16][132];
    const int bm = blockIdx.y * 128;
    const int bn = blockIdx.x * 128;
    const int tid = threadIdx.x;
    const int tx = tid & 15, ty = tid >> 4;
    const int lrow = tid >> 2, lcol = (tid & 3) * 4;
    const int krow = tid >> 5, ncol = (tid & 31) * 4;

#pragma unroll
    for (int p = 0; p < 2; p++) {
        float4 va = *(const float4*)&g_wc[(size_t)(bm + lrow + p * 64) * EE + lcol];
        STORE_T(As[0], va, p);
        float4 vb = *(const float4*)&Wout[(size_t)(krow + p * 8) * DD + bn + ncol];
        *(float4*)&Bs[0][krow + p * 8][ncol] = vb;
    }
    __syncthreads();

    float acc[8][8] = {};
    const int nt = (EE + DD) / 16;
    for (int t = 0; t < nt; ++t) {
        const int cur = t & 1, nxt = cur ^ 1;
        float4 pa[2], pb[2];
        if (t + 1 < nt) {
            const int k0 = (t + 1) * 16;
#pragma unroll
            for (int p = 0; p < 2; p++) {
                if (k0 < EE)
                    pa[p] = *(const float4*)&g_wc[(size_t)(bm + lrow + p * 64) * EE + k0 + lcol];
                else
                    pa[p] = *(const float4*)&dec[(size_t)(bm + lrow + p * 64) * DD + (k0 - EE) + lcol];
                pb[p] = *(const float4*)&Wout[(size_t)(k0 + krow + p * 8) * DD + bn + ncol];
            }
        }
        GEMM_COMPUTE(cur)
        if (t + 1 < nt) {
#pragma unroll
            for (int p = 0; p < 2; p++) {
                STORE_T(As[nxt], pa[p], p);
                *(float4*)&Bs[nxt][krow + p * 8][ncol] = pb[p];
            }
        }
        __syncthreads();
    }
#pragma unroll
    for (int i = 0; i < 8; i++) {
        const size_t m = bm + ty * 8 + i;
        float4 o0, o1;
        o0.x = tanhf(acc[i][0]); o0.y = tanhf(acc[i][1]);
        o0.z = tanhf(acc[i][2]); o0.w = tanhf(acc[i][3]);
        o1.x = tanhf(acc[i][4]); o1.y = tanhf(acc[i][5]);
        o1.z = tanhf(acc[i][6]); o1.w = tanhf(acc[i][7]);
        *(float4*)&ht[m * DD + bn + tx * 8]     = o0;
        *(float4*)&ht[m * DD + bn + tx * 8 + 4] = o1;
    }
}

extern "C" void kernel_launch(void* const* d_in, const int* in_sizes, int n_in,
                              void* d_out, int out_size)
{
    const float* dec    = (const float*)d_in[0];  // [B,T,DEC]
    const float* enc    = (const float*)d_in[1];  // [B,S,ENC]
    const int*   mask   = (const int*)d_in[2];    // [B,S]
    const float* W_attn = (const float*)d_in[3];  // [ENC,DEC]
    const float* b_attn = (const float*)d_in[4];  // [DEC]
    const float* W_out  = (const float*)d_in[5];  // [ENC+DEC,DEC]
    float* out = (float*)d_out;

    const size_t n_h    = (size_t)BB * TT * DD;
    const size_t n_attn = (size_t)BB * TT * SS;
    const size_t n_me   = (size_t)BB * TT * SS;

    float* h_tilde = out;
    float* attn;
    float* me;
    if ((size_t)out_size >= n_h + n_attn + n_me) {
        attn = out + n_h;
        me   = out + n_h + n_attn;
    } else {
        void* p;
        cudaGetSymbolAddress(&p, g_attn_scratch); attn = (float*)p;
        cudaGetSymbolAddress(&p, g_me_scratch);   me = (float*)p;
    }

    // 0. c = dec . b_attn
    k_c<<<dim3(BB * TT / 8), 256>>>(dec, b_attn);
    // 1. P = dec @ W_attn^T             M=8192 N=1024 K=512
    k_P<<<dim3(EE / 128, (BB * TT) / 128), 256>>>(dec, W_attn);
    // 2. masked energies = P @ enc^T    per-batch M=128 N=512 K=1024
    k_energy<<<dim3(SS / 128, 1, BB), 256>>>(enc, mask, me);
    // 3. softmax rows
    k_softmax<<<dim3(BB * TT), 256>>>(me, attn);
    // 4. weighted context               per-batch M=128 N=1024 K=512
    k_wc<<<dim3(EE / 128, 1, BB), 256>>>(attn, enc);
    // 5. h_tilde = tanh([wc, dec] @ W_out)  M=8192 K=1536 N=512
    k_out<<<dim3(DD / 128, (BB * TT) / 128), 256>>>(dec, W_out, h_tilde);
}

// round 4
// speedup vs baseline: 2.5485x; 1.4075x over previous
#include <cuda_runtime.h>
#include <cstdint>

// Problem constants (fixed by dataset)
#define BB 64
#define TT 128
#define SS 512
#define EE 1024
#define DD 512
#define NEGINF (-1.0e10f)
#define PAD 132

// Scratch (allocation-free rule: device globals)
__device__ float g_P[(size_t)BB * TT * EE];    // P = dec @ W_attn^T  [B*T, E]
__device__ float g_wc[(size_t)BB * TT * EE];   // weighted context    [B*T, E]
__device__ float g_c[(size_t)BB * TT];         // c = dec . b_attn    [B*T]
__device__ float g_attn_scratch[(size_t)BB * TT * SS];
__device__ float g_me_scratch[(size_t)BB * TT * SS];

// ---------------------------------------------------------------------------
// tf32 helpers
// ---------------------------------------------------------------------------
__device__ __forceinline__ float f2tf32(float x) {
    uint32_t u;
    asm("cvt.rna.tf32.f32 %0, %1;" : "=r"(u) : "f"(x));
    return __uint_as_float(u);
}

__device__ __forceinline__ void mma8(float* d, const float* a, const float* b) {
    asm volatile(
        "mma.sync.aligned.m16n8k8.row.col.f32.tf32.tf32.f32 "
        "{%0,%1,%2,%3}, {%4,%5,%6,%7}, {%8,%9}, {%0,%1,%2,%3};"
        : "+f"(d[0]), "+f"(d[1]), "+f"(d[2]), "+f"(d[3])
        : "r"(__float_as_uint(a[0])), "r"(__float_as_uint(a[1])),
          "r"(__float_as_uint(a[2])), "r"(__float_as_uint(a[3])),
          "r"(__float_as_uint(b[0])), "r"(__float_as_uint(b[1])));
}

// ---------------------------------------------------------------------------
// Staging macros. Transposed staging: gmem row-major [row][k] -> SMEM [k][row].
// lrow = tid>>2 (0..63), lcol = (tid&3)*4. Direct staging: [k][n] rows.
// ---------------------------------------------------------------------------
#define STAGE_T(H, v, p) do {                                   \
    const int _r = lrow + (p) * 64;                             \
    H[lcol + 0][_r] = f2tf32((v).x);                            \
    H[lcol + 1][_r] = f2tf32((v).y);                            \
    H[lcol + 2][_r] = f2tf32((v).z);                            \
    H[lcol + 3][_r] = f2tf32((v).w);                            \
} while (0)

#define STAGE_T_SPLIT(H, L, v, p) do {                          \
    const int _r = lrow + (p) * 64;                             \
    float _h;                                                   \
    _h = f2tf32((v).x); H[lcol+0][_r] = _h; L[lcol+0][_r] = f2tf32((v).x - _h); \
    _h = f2tf32((v).y); H[lcol+1][_r] = _h; L[lcol+1][_r] = f2tf32((v).y - _h); \
    _h = f2tf32((v).z); H[lcol+2][_r] = _h; L[lcol+2][_r] = f2tf32((v).z - _h); \
    _h = f2tf32((v).w); H[lcol+3][_r] = _h; L[lcol+3][_r] = f2tf32((v).w - _h); \
} while (0)

#define STAGE_D(H, v, p) do {                                   \
    float4 _cv;                                                 \
    _cv.x = f2tf32((v).x); _cv.y = f2tf32((v).y);               \
    _cv.z = f2tf32((v).z); _cv.w = f2tf32((v).w);               \
    *(float4*)&H[krow + (p) * 8][ncol] = _cv;                   \
} while (0)

// ---------------------------------------------------------------------------
// Compute macros: per 16-k tile, 2 k8 steps. Fragment layout per PTX m16n8k8.
// ---------------------------------------------------------------------------
#define COMPUTE_TILE(Ahb, Bhb)                                              \
    _Pragma("unroll")                                                       \
    for (int ks = 0; ks < 2; ks++) {                                        \
        const int k0 = ks * 8;                                              \
        float af[4][4], bf[4][2];                                           \
        _Pragma("unroll")                                                   \
        for (int mi = 0; mi < 4; mi++) {                                    \
            const int m = am0 + mi * 16 + qr;                               \
            af[mi][0] = Ahb[k0 + qc][m];     af[mi][1] = Ahb[k0 + qc][m + 8];   \
            af[mi][2] = Ahb[k0 + qc + 4][m]; af[mi][3] = Ahb[k0 + qc + 4][m + 8]; \
        }                                                                   \
        _Pragma("unroll")                                                   \
        for (int nj = 0; nj < 4; nj++) {                                    \
            const int n = bn0 + nj * 8 + qr;                                \
            bf[nj][0] = Bhb[k0 + qc][n]; bf[nj][1] = Bhb[k0 + qc + 4][n];   \
        }                                                                   \
        _Pragma("unroll")                                                   \
        for (int mi = 0; mi < 4; mi++)                                      \
            _Pragma("unroll")                                               \
            for (int nj = 0; nj < 4; nj++)                                  \
                mma8(acc[mi][nj], af[mi], bf[nj]);                          \
    }

#define COMPUTE_TILE_SPLIT(Ahb, Alb, Bhb, Blb)                              \
    _Pragma("unroll")                                                       \
    for (int ks = 0; ks < 2; ks++) {                                        \
        const int k0 = ks * 8;                                              \
        float ah[4][4], al[4][4], bh[4][2], bl[4][2];                       \
        _Pragma("unroll")                                                   \
        for (int mi = 0; mi < 4; mi++) {                                    \
            const int m = am0 + mi * 16 + qr;                               \
            ah[mi][0] = Ahb[k0 + qc][m];     ah[mi][1] = Ahb[k0 + qc][m + 8];   \
            ah[mi][2] = Ahb[k0 + qc + 4][m]; ah[mi][3] = Ahb[k0 + qc + 4][m + 8]; \
            al[mi][0] = Alb[k0 + qc][m];     al[mi][1] = Alb[k0 + qc][m + 8];   \
            al[mi][2] = Alb[k0 + qc + 4][m]; al[mi][3] = Alb[k0 + qc + 4][m + 8]; \
        }                                                                   \
        _Pragma("unroll")                                                   \
        for (int nj = 0; nj < 4; nj++) {                                    \
            const int n = bn0 + nj * 8 + qr;                                \
            bh[nj][0] = Bhb[k0 + qc][n]; bh[nj][1] = Bhb[k0 + qc + 4][n];   \
            bl[nj][0] = Blb[k0 + qc][n]; bl[nj][1] = Blb[k0 + qc + 4][n];   \
        }                                                                   \
        _Pragma("unroll")                                                   \
        for (int mi = 0; mi < 4; mi++)                                      \
            _Pragma("unroll")                                               \
            for (int nj = 0; nj < 4; nj++) {                                \
                mma8(acc[mi][nj], ah[mi], bh[nj]);                          \
                mma8(acc[mi][nj], ah[mi], bl[nj]);                          \
                mma8(acc[mi][nj], al[mi], bh[nj]);                          \
            }                                                               \
    }

#define WARP_IDX_SETUP                                  \
    const int tid = threadIdx.x;                        \
    const int lane = tid & 31, wid = tid >> 5;          \
    const int qr = lane >> 2, qc = lane & 3;            \
    const int am0 = (wid >> 2) * 64;                    \
    const int bn0 = (wid & 3) * 32;                     \
    const int lrow = tid >> 2, lcol = (tid & 3) * 4;    \
    const int krow = tid >> 5, ncol = (tid & 31) * 4;   \
    (void)krow; (void)ncol;

// Kernel c: c[m] = sum_d dec[m,d] * b_attn[d]
__global__ __launch_bounds__(256)
void k_c(const float* __restrict__ dec, const float* __restrict__ ba)
{
    const int m = blockIdx.x * 8 + (threadIdx.x >> 5);
    const int lane = threadIdx.x & 31;
    float s = 0.0f;
#pragma unroll
    for (int it = 0; it < 4; it++) {
        float4 v = *(const float4*)&dec[(size_t)m * DD + it * 128 + lane * 4];
        float4 w = *(const float4*)&ba[it * 128 + lane * 4];
        s += v.x * w.x + v.y * w.y + v.z * w.z + v.w * w.w;
    }
#pragma unroll
    for (int o = 16; o; o >>= 1) s += __shfl_xor_sync(0xffffffffu, s, o);
    if (lane == 0) g_c[m] = s;
}

// k_P (split tf32): P[m,e] = sum_d dec[m,d] * W[e,d]   M=8192, N=1024, K=512
__global__ __launch_bounds__(256)
void k_P(const float* __restrict__ dec, const float* __restrict__ W)
{
    __shared__ float Ah[16][PAD], Al[16][PAD], Bh[16][PAD], Bl[16][PAD];
    WARP_IDX_SETUP
    const int bm = blockIdx.y * 128, bn = blockIdx.x * 128;

    float4 va[2], vb[2];
#pragma unroll
    for (int p = 0; p < 2; p++) {
        va[p] = *(const float4*)&dec[(size_t)(bm + lrow + p * 64) * DD + lcol];
        vb[p] = *(const float4*)&W[(size_t)(bn + lrow + p * 64) * DD + lcol];
    }
    float acc[4][4][4] = {};
    const int nt = DD / 16;
    for (int t = 0; t < nt; t++) {
        STAGE_T_SPLIT(Ah, Al, va[0], 0); STAGE_T_SPLIT(Ah, Al, va[1], 1);
        STAGE_T_SPLIT(Bh, Bl, vb[0], 0); STAGE_T_SPLIT(Bh, Bl, vb[1], 1);
        __syncthreads();
        if (t + 1 < nt) {
            const int k0 = (t + 1) * 16;
#pragma unroll
            for (int p = 0; p < 2; p++) {
                va[p] = *(const float4*)&dec[(size_t)(bm + lrow + p * 64) * DD + k0 + lcol];
                vb[p] = *(const float4*)&W[(size_t)(bn + lrow + p * 64) * DD + k0 + lcol];
            }
        }
        COMPUTE_TILE_SPLIT(Ah, Al, Bh, Bl)
        __syncthreads();
    }
#pragma unroll
    for (int mi = 0; mi < 4; mi++)
#pragma unroll
        for (int nj = 0; nj < 4; nj++) {
            const size_t m = bm + am0 + mi * 16 + qr;
            const int n = bn + bn0 + nj * 8 + qc * 2;
            *(float2*)&g_P[m * EE + n]       = make_float2(acc[mi][nj][0], acc[mi][nj][1]);
            *(float2*)&g_P[(m + 8) * EE + n] = make_float2(acc[mi][nj][2], acc[mi][nj][3]);
        }
}

// k_energy (split tf32, per batch): me[t,s] = mask[s] ? P[t,:].enc[s,:] + c[t] : NEGINF
// M=128(T), N=128 per block (grid.x=4), K=1024
__global__ __launch_bounds__(256)
void k_energy(const float* __restrict__ enc, const int* __restrict__ mask,
              float* __restrict__ me)
{
    __shared__ float Ah[16][PAD], Al[16][PAD], Bh[16][PAD], Bl[16][PAD];
    WARP_IDX_SETUP
    const int b = blockIdx.z;
    const int bn = blockIdx.x * 128;
    const float* A = g_P + (size_t)b * TT * EE;
    const float* Ep = enc + (size_t)b * SS * EE;

    float4 va[2], vb[2];
#pragma unroll
    for (int p = 0; p < 2; p++) {
        va[p] = *(const float4*)&A[(size_t)(lrow + p * 64) * EE + lcol];
        vb[p] = *(const float4*)&Ep[(size_t)(bn + lrow + p * 64) * EE + lcol];
    }
    float acc[4][4][4] = {};
    const int nt = EE / 16;
    for (int t = 0; t < nt; t++) {
        STAGE_T_SPLIT(Ah, Al, va[0], 0); STAGE_T_SPLIT(Ah, Al, va[1], 1);
        STAGE_T_SPLIT(Bh, Bl, vb[0], 0); STAGE_T_SPLIT(Bh, Bl, vb[1], 1);
        __syncthreads();
        if (t + 1 < nt) {
            const int k0 = (t + 1) * 16;
#pragma unroll
            for (int p = 0; p < 2; p++) {
                va[p] = *(const float4*)&A[(size_t)(lrow + p * 64) * EE + k0 + lcol];
                vb[p] = *(const float4*)&Ep[(size_t)(bn + lrow + p * 64) * EE + k0 + lcol];
            }
        }
        COMPUTE_TILE_SPLIT(Ah, Al, Bh, Bl)
        __syncthreads();
    }
#pragma unroll
    for (int mi = 0; mi < 4; mi++) {
        const int t0 = am0 + mi * 16 + qr;
        const float ct0 = g_c[(size_t)b * TT + t0];
        const float ct1 = g_c[(size_t)b * TT + t0 + 8];
#pragma unroll
        for (int nj = 0; nj < 4; nj++) {
            const int s = bn + bn0 + nj * 8 + qc * 2;
            const int mk0 = mask[(size_t)b * SS + s];
            const int mk1 = mask[(size_t)b * SS + s + 1];
            float2 r0, r1;
            r0.x = mk0 ? acc[mi][nj][0] + ct0 : NEGINF;
            r0.y = mk1 ? acc[mi][nj][1] + ct0 : NEGINF;
            r1.x = mk0 ? acc[mi][nj][2] + ct1 : NEGINF;
            r1.y = mk1 ? acc[mi][nj][3] + ct1 : NEGINF;
            *(float2*)&me[((size_t)b * TT + t0) * SS + s]     = r0;
            *(float2*)&me[((size_t)b * TT + t0 + 8) * SS + s] = r1;
        }
    }
}

// Row softmax over S=512, one block (256 thr) per (b,t) row.
__global__ __launch_bounds__(256)
void k_softmax(const float* __restrict__ me, float* __restrict__ attn)
{
    const int row = blockIdx.x;
    const float* x = me + (size_t)row * SS;
    float* y = attn + (size_t)row * SS;
    const int tid = threadIdx.x;
    __shared__ float smax[8];
    __shared__ float ssum[8];

    float v0 = x[tid], v1 = x[tid + 256];
    float m = fmaxf(v0, v1);
#pragma unroll
    for (int o = 16; o; o >>= 1) m = fmaxf(m, __shfl_xor_sync(0xffffffffu, m, o));
    if ((tid & 31) == 0) smax[tid >> 5] = m;
    __syncthreads();
    float M = smax[0];
#pragma unroll
    for (int i = 1; i < 8; i++) M = fmaxf(M, smax[i]);

    float e0 = __expf(v0 - M), e1 = __expf(v1 - M);
    float s = e0 + e1;
#pragma unroll
    for (int o = 16; o; o >>= 1) s += __shfl_xor_sync(0xffffffffu, s, o);
    if ((tid & 31) == 0) ssum[tid >> 5] = s;
    __syncthreads();
    float S = 0.0f;
#pragma unroll
    for (int i = 0; i < 8; i++) S += ssum[i];
    float inv = 1.0f / S;
    y[tid] = e0 * inv;
    y[tid + 256] = e1 * inv;
}

// k_wc (tf32, per batch): wc[t,e] = sum_s attn[t,s]*enc[s,e]
// M=128(T), N=128 per block (grid.x=8), K=512. B direct [k=s][n=e].
__global__ __launch_bounds__(256)
void k_wc(const float* __restrict__ attn, const float* __restrict__ enc)
{
    __shared__ float Ah[16][PAD], Bh[16][PAD];
    WARP_IDX_SETUP
    const int b = blockIdx.z;
    const int bn = blockIdx.x * 128;
    const float* A = attn + (size_t)b * TT * SS;
    const float* Ep = enc + (size_t)b * SS * EE;

    float4 va[2], vb[2];
#pragma unroll
    for (int p = 0; p < 2; p++) {
        va[p] = *(const float4*)&A[(size_t)(lrow + p * 64) * SS + lcol];
        vb[p] = *(const float4*)&Ep[(size_t)(krow + p * 8) * EE + bn + ncol];
    }
    float acc[4][4][4] = {};
    const int nt = SS / 16;
    for (int t = 0; t < nt; t++) {
        STAGE_T(Ah, va[0], 0); STAGE_T(Ah, va[1], 1);
        STAGE_D(Bh, vb[0], 0); STAGE_D(Bh, vb[1], 1);
        __syncthreads();
        if (t + 1 < nt) {
            const int k0 = (t + 1) * 16;
#pragma unroll
            for (int p = 0; p < 2; p++) {
                va[p] = *(const float4*)&A[(size_t)(lrow + p * 64) * SS + k0 + lcol];
                vb[p] = *(const float4*)&Ep[(size_t)(k0 + krow + p * 8) * EE + bn + ncol];
            }
        }
        COMPUTE_TILE(Ah, Bh)
        __syncthreads();
    }
#pragma unroll
    for (int mi = 0; mi < 4; mi++)
#pragma unroll
        for (int nj = 0; nj < 4; nj++) {
            const size_t m = (size_t)b * TT + am0 + mi * 16 + qr;
            const int n = bn + bn0 + nj * 8 + qc * 2;
            *(float2*)&g_wc[m * EE + n]       = make_float2(acc[mi][nj][0], acc[mi][nj][1]);
            *(float2*)&g_wc[(m + 8) * EE + n] = make_float2(acc[mi][nj][2], acc[mi][nj][3]);
        }
}

// k_out (tf32): ht[m,n] = tanh([wc | dec][m,:] @ W_out[:,n])  M=8192, K=1536, N=512
__global__ __launch_bounds__(256)
void k_out(const float* __restrict__ dec, const float* __restrict__ Wout,
           float* __restrict__ ht)
{
    __shared__ float Ah[16][PAD], Bh[16][PAD];
    WARP_IDX_SETUP
    const int bm = blockIdx.y * 128, bn = blockIdx.x * 128;

    float4 va[2], vb[2];
#pragma unroll
    for (int p = 0; p < 2; p++) {
        va[p] = *(const float4*)&g_wc[(size_t)(bm + lrow + p * 64) * EE + lcol];
        vb[p] = *(const float4*)&Wout[(size_t)(krow + p * 8) * DD + bn + ncol];
    }
    float acc[4][4][4] = {};
    const int nt = (EE + DD) / 16;
    for (int t = 0; t < nt; t++) {
        STAGE_T(Ah, va[0], 0); STAGE_T(Ah, va[1], 1);
        STAGE_D(Bh, vb[0], 0); STAGE_D(Bh, vb[1], 1);
        __syncthreads();
        if (t + 1 < nt) {
            const int k0 = (t + 1) * 16;
#pragma unroll
            for (int p = 0; p < 2; p++) {
                if (k0 < EE)
                    va[p] = *(const float4*)&g_wc[(size_t)(bm + lrow + p * 64) * EE + k0 + lcol];
                else
                    va[p] = *(const float4*)&dec[(size_t)(bm + lrow + p * 64) * DD + (k0 - EE) + lcol];
                vb[p] = *(const float4*)&Wout[(size_t)(k0 + krow + p * 8) * DD + bn + ncol];
            }
        }
        COMPUTE_TILE(Ah, Bh)
        __syncthreads();
    }
#pragma unroll
    for (int mi = 0; mi < 4; mi++)
#pragma unroll
        for (int nj = 0; nj < 4; nj++) {
            const size_t m = bm + am0 + mi * 16 + qr;
            const int n = bn + bn0 + nj * 8 + qc * 2;
            float2 r0 = make_float2(tanhf(acc[mi][nj][0]), tanhf(acc[mi][nj][1]));
            float2 r1 = make_float2(tanhf(acc[mi][nj][2]), tanhf(acc[mi][nj][3]));
            *(float2*)&ht[m * DD + n]       = r0;
            *(float2*)&ht[(m + 8) * DD + n] = r1;
        }
}

extern "C" void kernel_launch(void* const* d_in, const int* in_sizes, int n_in,
                              void* d_out, int out_size)
{
    const float* dec    = (const float*)d_in[0];  // [B,T,DEC]
    const float* enc    = (const float*)d_in[1];  // [B,S,ENC]
    const int*   mask   = (const int*)d_in[2];    // [B,S]
    const float* W_attn = (const float*)d_in[3];  // [ENC,DEC]
    const float* b_attn = (const float*)d_in[4];  // [DEC]
    const float* W_out  = (const float*)d_in[5];  // [ENC+DEC,DEC]
    float* out = (float*)d_out;

    const size_t n_h    = (size_t)BB * TT * DD;
    const size_t n_attn = (size_t)BB * TT * SS;
    const size_t n_me   = (size_t)BB * TT * SS;

    float* h_tilde = out;
    float* attn;
    float* me;
    if ((size_t)out_size >= n_h + n_attn + n_me) {
        attn = out + n_h;
        me   = out + n_h + n_attn;
    } else {
        void* p;
        cudaGetSymbolAddress(&p, g_attn_scratch); attn = (float*)p;
        cudaGetSymbolAddress(&p, g_me_scratch);   me = (float*)p;
    }

    // 0. c = dec . b_attn
    k_c<<<dim3(BB * TT / 8), 256>>>(dec, b_attn);
    // 1. P = dec @ W_attn^T (split tf32)      M=8192 N=1024 K=512
    k_P<<<dim3(EE / 128, (BB * TT) / 128), 256>>>(dec, W_attn);
    // 2. masked energies = P @ enc^T (split)  per-batch M=128 N=512 K=1024
    k_energy<<<dim3(SS / 128, 1, BB), 256>>>(enc, mask, me);
    // 3. softmax rows
    k_softmax<<<dim3(BB * TT), 256>>>(me, attn);
    // 4. weighted context (tf32)              per-batch M=128 N=1024 K=512
    k_wc<<<dim3(EE / 128, 1, BB), 256>>>(attn, enc);
    // 5. h_tilde = tanh([wc, dec] @ W_out)    M=8192 K=1536 N=512
    k_out<<<dim3(DD / 128, (BB * TT) / 128), 256>>>(dec, W_out, h_tilde);
}

// round 5
// speedup vs baseline: 2.6679x; 1.0468x over previous
#include <cuda_runtime.h>
#include <cstdint>

// Problem constants (fixed by dataset)
#define BB 64
#define TT 128
#define SS 512
#define EE 1024
#define DD 512
#define NEGINF (-1.0e10f)
#define PAD 132
#define SZ (16 * PAD)

// Scratch (allocation-free rule: device globals)
__device__ float g_P[(size_t)BB * TT * EE];    // P = dec @ W_attn^T  [B*T, E]
__device__ float g_wc[(size_t)BB * TT * EE];   // weighted context    [B*T, E]
__device__ float g_c[(size_t)BB * TT];         // c = dec . b_attn    [B*T]
__device__ float g_attn_scratch[(size_t)BB * TT * SS];
__device__ float g_me_scratch[(size_t)BB * TT * SS];

// ---------------------------------------------------------------------------
// tf32 helpers
// ---------------------------------------------------------------------------
__device__ __forceinline__ float f2tf32(float x) {
    uint32_t u;
    asm("cvt.rna.tf32.f32 %0, %1;" : "=r"(u) : "f"(x));
    return __uint_as_float(u);
}

__device__ __forceinline__ void mma8(float* d, const float* a, const float* b) {
    asm volatile(
        "mma.sync.aligned.m16n8k8.row.col.f32.tf32.tf32.f32 "
        "{%0,%1,%2,%3}, {%4,%5,%6,%7}, {%8,%9}, {%0,%1,%2,%3};"
        : "+f"(d[0]), "+f"(d[1]), "+f"(d[2]), "+f"(d[3])
        : "r"(__float_as_uint(a[0])), "r"(__float_as_uint(a[1])),
          "r"(__float_as_uint(a[2])), "r"(__float_as_uint(a[3])),
          "r"(__float_as_uint(b[0])), "r"(__float_as_uint(b[1])));
}

// ---------------------------------------------------------------------------
// Staging. Transposed: gmem row-major [row][k] -> SMEM [k][row].
// lrow = tid>>2 (0..63), lcol = (tid&3)*4. Direct: [k][n] rows.
// Pointer variants (dynamic smem) index H[(k)*PAD + r].
// ---------------------------------------------------------------------------
#define STAGE_T(H, v, p) do {                                   \
    const int _r = lrow + (p) * 64;                             \
    H[lcol + 0][_r] = f2tf32((v).x);                            \
    H[lcol + 1][_r] = f2tf32((v).y);                            \
    H[lcol + 2][_r] = f2tf32((v).z);                            \
    H[lcol + 3][_r] = f2tf32((v).w);                            \
} while (0)

#define STAGE_T_SPLIT_P(Hp, Lp, v, p) do {                      \
    const int _r = lrow + (p) * 64;                             \
    float _h;                                                   \
    _h = f2tf32((v).x); Hp[(lcol+0)*PAD+_r] = _h; Lp[(lcol+0)*PAD+_r] = f2tf32((v).x - _h); \
    _h = f2tf32((v).y); Hp[(lcol+1)*PAD+_r] = _h; Lp[(lcol+1)*PAD+_r] = f2tf32((v).y - _h); \
    _h = f2tf32((v).z); Hp[(lcol+2)*PAD+_r] = _h; Lp[(lcol+2)*PAD+_r] = f2tf32((v).z - _h); \
    _h = f2tf32((v).w); Hp[(lcol+3)*PAD+_r] = _h; Lp[(lcol+3)*PAD+_r] = f2tf32((v).w - _h); \
} while (0)

#define STAGE_D(H, v, p) do {                                   \
    float4 _cv;                                                 \
    _cv.x = f2tf32((v).x); _cv.y = f2tf32((v).y);               \
    _cv.z = f2tf32((v).z); _cv.w = f2tf32((v).w);               \
    *(float4*)&H[krow + (p) * 8][ncol] = _cv;                   \
} while (0)

// ---------------------------------------------------------------------------
// Compute: per 16-k tile, 2 k8 steps. Fragment layout per PTX m16n8k8.
// ---------------------------------------------------------------------------
#define COMPUTE_TILE(Ahb, Bhb)                                              \
    _Pragma("unroll")                                                       \
    for (int ks = 0; ks < 2; ks++) {                                        \
        const int k0 = ks * 8;                                              \
        float af[4][4], bf[4][2];                                           \
        _Pragma("unroll")                                                   \
        for (int mi = 0; mi < 4; mi++) {                                    \
            const int m = am0 + mi * 16 + qr;                               \
            af[mi][0] = Ahb[k0 + qc][m];     af[mi][1] = Ahb[k0 + qc][m + 8];   \
            af[mi][2] = Ahb[k0 + qc + 4][m]; af[mi][3] = Ahb[k0 + qc + 4][m + 8]; \
        }                                                                   \
        _Pragma("unroll")                                                   \
        for (int nj = 0; nj < 4; nj++) {                                    \
            const int n = bn0 + nj * 8 + qr;                                \
            bf[nj][0] = Bhb[k0 + qc][n]; bf[nj][1] = Bhb[k0 + qc + 4][n];   \
        }                                                                   \
        _Pragma("unroll")                                                   \
        for (int mi = 0; mi < 4; mi++)                                      \
            _Pragma("unroll")                                               \
            for (int nj = 0; nj < 4; nj++)                                  \
                mma8(acc[mi][nj], af[mi], bf[nj]);                          \
    }

#define COMPUTE_TILE_SPLIT_P(Ahp, Alp, Bhp, Blp)                            \
    _Pragma("unroll")                                                       \
    for (int ks = 0; ks < 2; ks++) {                                        \
        const int k0 = ks * 8;                                              \
        float ah[4][4], al[4][4], bh[4][2], bl[4][2];                       \
        _Pragma("unroll")                                                   \
        for (int mi = 0; mi < 4; mi++) {                                    \
            const int m = am0 + mi * 16 + qr;                               \
            ah[mi][0] = Ahp[(k0+qc)*PAD + m];     ah[mi][1] = Ahp[(k0+qc)*PAD + m + 8];   \
            ah[mi][2] = Ahp[(k0+qc+4)*PAD + m];   ah[mi][3] = Ahp[(k0+qc+4)*PAD + m + 8]; \
            al[mi][0] = Alp[(k0+qc)*PAD + m];     al[mi][1] = Alp[(k0+qc)*PAD + m + 8];   \
            al[mi][2] = Alp[(k0+qc+4)*PAD + m];   al[mi][3] = Alp[(k0+qc+4)*PAD + m + 8]; \
        }                                                                   \
        _Pragma("unroll")                                                   \
        for (int nj = 0; nj < 4; nj++) {                                    \
            const int n = bn0 + nj * 8 + qr;                                \
            bh[nj][0] = Bhp[(k0+qc)*PAD + n]; bh[nj][1] = Bhp[(k0+qc+4)*PAD + n]; \
            bl[nj][0] = Blp[(k0+qc)*PAD + n]; bl[nj][1] = Blp[(k0+qc+4)*PAD + n]; \
        }                                                                   \
        _Pragma("unroll")                                                   \
        for (int mi = 0; mi < 4; mi++)                                      \
            _Pragma("unroll")                                               \
            for (int nj = 0; nj < 4; nj++) {                                \
                mma8(acc[mi][nj], ah[mi], bh[nj]);                          \
                mma8(acc[mi][nj], ah[mi], bl[nj]);                          \
                mma8(acc[mi][nj], al[mi], bh[nj]);                          \
            }                                                               \
    }

#define WARP_IDX_SETUP                                  \
    const int tid = threadIdx.x;                        \
    const int lane = tid & 31, wid = tid >> 5;          \
    const int qr = lane >> 2, qc = lane & 3;            \
    const int am0 = (wid >> 2) * 64;                    \
    const int bn0 = (wid & 3) * 32;                     \
    const int lrow = tid >> 2, lcol = (tid & 3) * 4;    \
    const int krow = tid >> 5, ncol = (tid & 31) * 4;   \
    (void)krow; (void)ncol;

// Kernel c: c[m] = sum_d dec[m,d] * b_attn[d]
__global__ __launch_bounds__(256)
void k_c(const float* __restrict__ dec, const float* __restrict__ ba)
{
    const int m = blockIdx.x * 8 + (threadIdx.x >> 5);
    const int lane = threadIdx.x & 31;
    float s = 0.0f;
#pragma unroll
    for (int it = 0; it < 4; it++) {
        float4 v = *(const float4*)&dec[(size_t)m * DD + it * 128 + lane * 4];
        float4 w = *(const float4*)&ba[it * 128 + lane * 4];
        s += v.x * w.x + v.y * w.y + v.z * w.z + v.w * w.w;
    }
#pragma unroll
    for (int o = 16; o; o >>= 1) s += __shfl_xor_sync(0xffffffffu, s, o);
    if (lane == 0) g_c[m] = s;
}

// k_P (split tf32, double-buffered): P[m,e] = sum_d dec[m,d]*W[e,d]
// M=8192, N=1024, K=512. Dynamic smem: 8 regions of SZ floats.
__global__ __launch_bounds__(256)
void k_P(const float* __restrict__ dec, const float* __restrict__ W)
{
    extern __shared__ float sm[];
    WARP_IDX_SETUP
    const int bm = blockIdx.y * 128, bn = blockIdx.x * 128;

    float4 va[2], vb[2];
#pragma unroll
    for (int p = 0; p < 2; p++) {
        va[p] = *(const float4*)&dec[(size_t)(bm + lrow + p * 64) * DD + lcol];
        vb[p] = *(const float4*)&W[(size_t)(bn + lrow + p * 64) * DD + lcol];
    }
    {
        float* Ahn = sm;            float* Aln = sm + 2 * SZ;
        float* Bhn = sm + 4 * SZ;   float* Bln = sm + 6 * SZ;
        STAGE_T_SPLIT_P(Ahn, Aln, va[0], 0); STAGE_T_SPLIT_P(Ahn, Aln, va[1], 1);
        STAGE_T_SPLIT_P(Bhn, Bln, vb[0], 0); STAGE_T_SPLIT_P(Bhn, Bln, vb[1], 1);
    }
    __syncthreads();

    float acc[4][4][4] = {};
    const int nt = DD / 16;
    for (int t = 0; t < nt; t++) {
        const int cur = t & 1, nxt = cur ^ 1;
        const bool more = (t + 1 < nt);
        if (more) {
            const int k0 = (t + 1) * 16;
#pragma unroll
            for (int p = 0; p < 2; p++) {
                va[p] = *(const float4*)&dec[(size_t)(bm + lrow + p * 64) * DD + k0 + lcol];
                vb[p] = *(const float4*)&W[(size_t)(bn + lrow + p * 64) * DD + k0 + lcol];
            }
        }
        {
            const float* Ahc = sm + cur * SZ;        const float* Alc = sm + (2 + cur) * SZ;
            const float* Bhc = sm + (4 + cur) * SZ;  const float* Blc = sm + (6 + cur) * SZ;
            COMPUTE_TILE_SPLIT_P(Ahc, Alc, Bhc, Blc)
        }
        if (more) {
            float* Ahn = sm + nxt * SZ;        float* Aln = sm + (2 + nxt) * SZ;
            float* Bhn = sm + (4 + nxt) * SZ;  float* Bln = sm + (6 + nxt) * SZ;
            STAGE_T_SPLIT_P(Ahn, Aln, va[0], 0); STAGE_T_SPLIT_P(Ahn, Aln, va[1], 1);
            STAGE_T_SPLIT_P(Bhn, Bln, vb[0], 0); STAGE_T_SPLIT_P(Bhn, Bln, vb[1], 1);
        }
        __syncthreads();
    }
#pragma unroll
    for (int mi = 0; mi < 4; mi++)
#pragma unroll
        for (int nj = 0; nj < 4; nj++) {
            const size_t m = bm + am0 + mi * 16 + qr;
            const int n = bn + bn0 + nj * 8 + qc * 2;
            *(float2*)&g_P[m * EE + n]       = make_float2(acc[mi][nj][0], acc[mi][nj][1]);
            *(float2*)&g_P[(m + 8) * EE + n] = make_float2(acc[mi][nj][2], acc[mi][nj][3]);
        }
}

// k_energy (split tf32, double-buffered, per batch):
// me[t,s] = mask[s] ? P[t,:].enc[s,:] + c[t] : NEGINF.  M=128, N=128/blk, K=1024
__global__ __launch_bounds__(256)
void k_energy(const float* __restrict__ enc, const int* __restrict__ mask,
              float* __restrict__ me)
{
    extern __shared__ float sm[];
    WARP_IDX_SETUP
    const int b = blockIdx.z;
    const int bn = blockIdx.x * 128;
    const float* A = g_P + (size_t)b * TT * EE;
    const float* Ep = enc + (size_t)b * SS * EE;

    float4 va[2], vb[2];
#pragma unroll
    for (int p = 0; p < 2; p++) {
        va[p] = *(const float4*)&A[(size_t)(lrow + p * 64) * EE + lcol];
        vb[p] = *(const float4*)&Ep[(size_t)(bn + lrow + p * 64) * EE + lcol];
    }
    {
        float* Ahn = sm;            float* Aln = sm + 2 * SZ;
        float* Bhn = sm + 4 * SZ;   float* Bln = sm + 6 * SZ;
        STAGE_T_SPLIT_P(Ahn, Aln, va[0], 0); STAGE_T_SPLIT_P(Ahn, Aln, va[1], 1);
        STAGE_T_SPLIT_P(Bhn, Bln, vb[0], 0); STAGE_T_SPLIT_P(Bhn, Bln, vb[1], 1);
    }
    __syncthreads();

    float acc[4][4][4] = {};
    const int nt = EE / 16;
    for (int t = 0; t < nt; t++) {
        const int cur = t & 1, nxt = cur ^ 1;
        const bool more = (t + 1 < nt);
        if (more) {
            const int k0 = (t + 1) * 16;
#pragma unroll
            for (int p = 0; p < 2; p++) {
                va[p] = *(const float4*)&A[(size_t)(lrow + p * 64) * EE + k0 + lcol];
                vb[p] = *(const float4*)&Ep[(size_t)(bn + lrow + p * 64) * EE + k0 + lcol];
            }
        }
        {
            const float* Ahc = sm + cur * SZ;        const float* Alc = sm + (2 + cur) * SZ;
            const float* Bhc = sm + (4 + cur) * SZ;  const float* Blc = sm + (6 + cur) * SZ;
            COMPUTE_TILE_SPLIT_P(Ahc, Alc, Bhc, Blc)
        }
        if (more) {
            float* Ahn = sm + nxt * SZ;        float* Aln = sm + (2 + nxt) * SZ;
            float* Bhn = sm + (4 + nxt) * SZ;  float* Bln = sm + (6 + nxt) * SZ;
            STAGE_T_SPLIT_P(Ahn, Aln, va[0], 0); STAGE_T_SPLIT_P(Ahn, Aln, va[1], 1);
            STAGE_T_SPLIT_P(Bhn, Bln, vb[0], 0); STAGE_T_SPLIT_P(Bhn, Bln, vb[1], 1);
        }
        __syncthreads();
    }
#pragma unroll
    for (int mi = 0; mi < 4; mi++) {
        const int t0 = am0 + mi * 16 + qr;
        const float ct0 = g_c[(size_t)b * TT + t0];
        const float ct1 = g_c[(size_t)b * TT + t0 + 8];
#pragma unroll
        for (int nj = 0; nj < 4; nj++) {
            const int s = bn + bn0 + nj * 8 + qc * 2;
            const int mk0 = mask[(size_t)b * SS + s];
            const int mk1 = mask[(size_t)b * SS + s + 1];
            float2 r0, r1;
            r0.x = mk0 ? acc[mi][nj][0] + ct0 : NEGINF;
            r0.y = mk1 ? acc[mi][nj][1] + ct0 : NEGINF;
            r1.x = mk0 ? acc[mi][nj][2] + ct1 : NEGINF;
            r1.y = mk1 ? acc[mi][nj][3] + ct1 : NEGINF;
            *(float2*)&me[((size_t)b * TT + t0) * SS + s]     = r0;
            *(float2*)&me[((size_t)b * TT + t0 + 8) * SS + s] = r1;
        }
    }
}

// Row softmax over S=512, one block (256 thr) per (b,t) row.
__global__ __launch_bounds__(256)
void k_softmax(const float* __restrict__ me, float* __restrict__ attn)
{
    const int row = blockIdx.x;
    const float* x = me + (size_t)row * SS;
    float* y = attn + (size_t)row * SS;
    const int tid = threadIdx.x;
    __shared__ float smax[8];
    __shared__ float ssum[8];

    float v0 = x[tid], v1 = x[tid + 256];
    float m = fmaxf(v0, v1);
#pragma unroll
    for (int o = 16; o; o >>= 1) m = fmaxf(m, __shfl_xor_sync(0xffffffffu, m, o));
    if ((tid & 31) == 0) smax[tid >> 5] = m;
    __syncthreads();
    float M = smax[0];
#pragma unroll
    for (int i = 1; i < 8; i++) M = fmaxf(M, smax[i]);

    float e0 = __expf(v0 - M), e1 = __expf(v1 - M);
    float s = e0 + e1;
#pragma unroll
    for (int o = 16; o; o >>= 1) s += __shfl_xor_sync(0xffffffffu, s, o);
    if ((tid & 31) == 0) ssum[tid >> 5] = s;
    __syncthreads();
    float S = 0.0f;
#pragma unroll
    for (int i = 0; i < 8; i++) S += ssum[i];
    float inv = 1.0f / S;
    y[tid] = e0 * inv;
    y[tid + 256] = e1 * inv;
}

// k_wc (tf32, double-buffered, per batch): wc[t,e] = sum_s attn[t,s]*enc[s,e]
// M=128, N=128/blk, K=512. B direct [k=s][n=e].
__global__ __launch_bounds__(256)
void k_wc(const float* __restrict__ attn, const float* __restrict__ enc)
{
    __shared__ float Ah[2][16][PAD], Bh[2][16][PAD];
    WARP_IDX_SETUP
    const int b = blockIdx.z;
    const int bn = blockIdx.x * 128;
    const float* A = attn + (size_t)b * TT * SS;
    const float* Ep = enc + (size_t)b * SS * EE;

    float4 va[2], vb[2];
#pragma unroll
    for (int p = 0; p < 2; p++) {
        va[p] = *(const float4*)&A[(size_t)(lrow + p * 64) * SS + lcol];
        vb[p] = *(const float4*)&Ep[(size_t)(krow + p * 8) * EE + bn + ncol];
    }
    STAGE_T(Ah[0], va[0], 0); STAGE_T(Ah[0], va[1], 1);
    STAGE_D(Bh[0], vb[0], 0); STAGE_D(Bh[0], vb[1], 1);
    __syncthreads();

    float acc[4][4][4] = {};
    const int nt = SS / 16;
    for (int t = 0; t < nt; t++) {
        const int cur = t & 1, nxt = cur ^ 1;
        const bool more = (t + 1 < nt);
        if (more) {
            const int k0 = (t + 1) * 16;
#pragma unroll
            for (int p = 0; p < 2; p++) {
                va[p] = *(const float4*)&A[(size_t)(lrow + p * 64) * SS + k0 + lcol];
                vb[p] = *(const float4*)&Ep[(size_t)(k0 + krow + p * 8) * EE + bn + ncol];
            }
        }
        COMPUTE_TILE(Ah[cur], Bh[cur])
        if (more) {
            STAGE_T(Ah[nxt], va[0], 0); STAGE_T(Ah[nxt], va[1], 1);
            STAGE_D(Bh[nxt], vb[0], 0); STAGE_D(Bh[nxt], vb[1], 1);
        }
        __syncthreads();
    }
#pragma unroll
    for (int mi = 0; mi < 4; mi++)
#pragma unroll
        for (int nj = 0; nj < 4; nj++) {
            const size_t m = (size_t)b * TT + am0 + mi * 16 + qr;
            const int n = bn + bn0 + nj * 8 + qc * 2;
            *(float2*)&g_wc[m * EE + n]       = make_float2(acc[mi][nj][0], acc[mi][nj][1]);
            *(float2*)&g_wc[(m + 8) * EE + n] = make_float2(acc[mi][nj][2], acc[mi][nj][3]);
        }
}

// k_out (tf32, double-buffered): ht[m,n] = tanh([wc | dec][m,:] @ W_out[:,n])
// M=8192, K=1536, N=512.
__global__ __launch_bounds__(256)
void k_out(const float* __restrict__ dec, const float* __restrict__ Wout,
           float* __restrict__ ht)
{
    __shared__ float Ah[2][16][PAD], Bh[2][16][PAD];
    WARP_IDX_SETUP
    const int bm = blockIdx.y * 128, bn = blockIdx.x * 128;

    float4 va[2], vb[2];
#pragma unroll
    for (int p = 0; p < 2; p++) {
        va[p] = *(const float4*)&g_wc[(size_t)(bm + lrow + p * 64) * EE + lcol];
        vb[p] = *(const float4*)&Wout[(size_t)(krow + p * 8) * DD + bn + ncol];
    }
    STAGE_T(Ah[0], va[0], 0); STAGE_T(Ah[0], va[1], 1);
    STAGE_D(Bh[0], vb[0], 0); STAGE_D(Bh[0], vb[1], 1);
    __syncthreads();

    float acc[4][4][4] = {};
    const int nt = (EE + DD) / 16;
    for (int t = 0; t < nt; t++) {
        const int cur = t & 1, nxt = cur ^ 1;
        const bool more = (t + 1 < nt);
        if (more) {
            const int k0 = (t + 1) * 16;
#pragma unroll
            for (int p = 0; p < 2; p++) {
                if (k0 < EE)
                    va[p] = *(const float4*)&g_wc[(size_t)(bm + lrow + p * 64) * EE + k0 + lcol];
                else
                    va[p] = *(const float4*)&dec[(size_t)(bm + lrow + p * 64) * DD + (k0 - EE) + lcol];
                vb[p] = *(const float4*)&Wout[(size_t)(k0 + krow + p * 8) * DD + bn + ncol];
            }
        }
        COMPUTE_TILE(Ah[cur], Bh[cur])
        if (more) {
            STAGE_T(Ah[nxt], va[0], 0); STAGE_T(Ah[nxt], va[1], 1);
            STAGE_D(Bh[nxt], vb[0], 0); STAGE_D(Bh[nxt], vb[1], 1);
        }
        __syncthreads();
    }
#pragma unroll
    for (int mi = 0; mi < 4; mi++)
#pragma unroll
        for (int nj = 0; nj < 4; nj++) {
            const size_t m = bm + am0 + mi * 16 + qr;
            const int n = bn + bn0 + nj * 8 + qc * 2;
            float2 r0 = make_float2(tanhf(acc[mi][nj][0]), tanhf(acc[mi][nj][1]));
            float2 r1 = make_float2(tanhf(acc[mi][nj][2]), tanhf(acc[mi][nj][3]));
            *(float2*)&ht[m * DD + n]       = r0;
            *(float2*)&ht[(m + 8) * DD + n] = r1;
        }
}

extern "C" void kernel_launch(void* const* d_in, const int* in_sizes, int n_in,
                              void* d_out, int out_size)
{
    const float* dec    = (const float*)d_in[0];  // [B,T,DEC]
    const float* enc    = (const float*)d_in[1];  // [B,S,ENC]
    const int*   mask   = (const int*)d_in[2];    // [B,S]
    const float* W_attn = (const float*)d_in[3];  // [ENC,DEC]
    const float* b_attn = (const float*)d_in[4];  // [DEC]
    const float* W_out  = (const float*)d_in[5];  // [ENC+DEC,DEC]
    float* out = (float*)d_out;

    const size_t n_h    = (size_t)BB * TT * DD;
    const size_t n_attn = (size_t)BB * TT * SS;
    const size_t n_me   = (size_t)BB * TT * SS;

    float* h_tilde = out;
    float* attn;
    float* me;
    if ((size_t)out_size >= n_h + n_attn + n_me) {
        attn = out + n_h;
        me   = out + n_h + n_attn;
    } else {
        void* p;
        cudaGetSymbolAddress(&p, g_attn_scratch); attn = (float*)p;
        cudaGetSymbolAddress(&p, g_me_scratch);   me = (float*)p;
    }

    const int smem_split = 8 * SZ * sizeof(float);  // 67584 B
    cudaFuncSetAttribute(k_P, cudaFuncAttributeMaxDynamicSharedMemorySize, smem_split);
    cudaFuncSetAttribute(k_energy, cudaFuncAttributeMaxDynamicSharedMemorySize, smem_split);

    // 0. c = dec . b_attn
    k_c<<<dim3(BB * TT / 8), 256>>>(dec, b_attn);
    // 1. P = dec @ W_attn^T (split tf32)      M=8192 N=1024 K=512
    k_P<<<dim3(EE / 128, (BB * TT) / 128), 256, smem_split>>>(dec, W_attn);
    // 2. masked energies = P @ enc^T (split)  per-batch M=128 N=512 K=1024
    k_energy<<<dim3(SS / 128, 1, BB), 256, smem_split>>>(enc, mask, me);
    // 3. softmax rows
    k_softmax<<<dim3(BB * TT), 256>>>(me, attn);
    // 4. weighted context (tf32)              per-batch M=128 N=1024 K=512
    k_wc<<<dim3(EE / 128, 1, BB), 256>>>(attn, enc);
    // 5. h_tilde = tanh([wc, dec] @ W_out)    M=8192 K=1536 N=512
    k_out<<<dim3(DD / 128, (BB * TT) / 128), 256>>>(dec, W_out, h_tilde);
}

// round 8
// speedup vs baseline: 3.5757x; 1.3403x over previous
#include <cuda_runtime.h>
#include <cstdint>

// Problem constants (fixed by dataset)
#define BB 64
#define TT 128
#define SS 512
#define EE 1024
#define DD 512
#define NEGINF (-1.0e10f)
#define PAD 132

// Scratch (allocation-free rule: device globals)
__device__ float g_P[(size_t)BB * TT * EE];    // P = dec @ W_attn^T  [B*T, E]
__device__ float g_wc[(size_t)BB * TT * EE];   // weighted context    [B*T, E]
__device__ float g_c[(size_t)BB * TT];         // c = dec . b_attn    [B*T]
__device__ float g_attn_scratch[(size_t)BB * TT * SS];
__device__ float g_me_scratch[(size_t)BB * TT * SS];

// ---------------------------------------------------------------------------
// mma helpers
// ---------------------------------------------------------------------------
__device__ __forceinline__ float f2tf32(float x) {
    uint32_t u;
    asm("cvt.rna.tf32.f32 %0, %1;" : "=r"(u) : "f"(x));
    return __uint_as_float(u);
}

__device__ __forceinline__ void mma8(float* d, const float* a, const float* b) {
    asm volatile(
        "mma.sync.aligned.m16n8k8.row.col.f32.tf32.tf32.f32 "
        "{%0,%1,%2,%3}, {%4,%5,%6,%7}, {%8,%9}, {%0,%1,%2,%3};"
        : "+f"(d[0]), "+f"(d[1]), "+f"(d[2]), "+f"(d[3])
        : "r"(__float_as_uint(a[0])), "r"(__float_as_uint(a[1])),
          "r"(__float_as_uint(a[2])), "r"(__float_as_uint(a[3])),
          "r"(__float_as_uint(b[0])), "r"(__float_as_uint(b[1])));
}

// bf16 m16n8k16 (one K16 step per call)
__device__ __forceinline__ void mma16(float* d, const uint32_t* a, const uint32_t* b) {
    asm volatile(
        "mma.sync.aligned.m16n8k16.row.col.f32.bf16.bf16.f32 "
        "{%0,%1,%2,%3}, {%4,%5,%6,%7}, {%8,%9}, {%0,%1,%2,%3};"
        : "+f"(d[0]), "+f"(d[1]), "+f"(d[2]), "+f"(d[3])
        : "r"(a[0]), "r"(a[1]), "r"(a[2]), "r"(a[3]), "r"(b[0]), "r"(b[1]));
}

// ---------------------------------------------------------------------------
// bf16 split staging: float4 (4 consecutive k) -> 2 hi-pairs + 2 lo-pairs,
// stored [kpair][row] (row-contiguous, PAD u32 row stride).
// lrow = tid>>2 (0..63), skp = (tid&3)*2.
// ---------------------------------------------------------------------------
#define STAGE_BF_SPLIT(Hb, Lb, v, p) do {                                     \
    const int _r = lrow + (p) * 64;                                           \
    uint32_t _h0, _h1, _l0, _l1;                                              \
    asm("cvt.rn.satfinite.bf16x2.f32 %0, %1, %2;" : "=r"(_h0)                 \
        : "f"((v).y), "f"((v).x));                                            \
    asm("cvt.rn.satfinite.bf16x2.f32 %0, %1, %2;" : "=r"(_h1)                 \
        : "f"((v).w), "f"((v).z));                                            \
    const float _hx = __uint_as_float(_h0 << 16);                             \
    const float _hy = __uint_as_float(_h0 & 0xFFFF0000u);                     \
    const float _hz = __uint_as_float(_h1 << 16);                             \
    const float _hw = __uint_as_float(_h1 & 0xFFFF0000u);                     \
    asm("cvt.rn.satfinite.bf16x2.f32 %0, %1, %2;" : "=r"(_l0)                 \
        : "f"((v).y - _hy), "f"((v).x - _hx));                                \
    asm("cvt.rn.satfinite.bf16x2.f32 %0, %1, %2;" : "=r"(_l1)                 \
        : "f"((v).w - _hw), "f"((v).z - _hz));                                \
    Hb[skp][_r] = _h0; Hb[skp + 1][_r] = _h1;                                 \
    Lb[skp][_r] = _l0; Lb[skp + 1][_r] = _l1;                                 \
} while (0)

// One K16 chunk of bf16 2-term split (hi*hi + hi*lo + lo*hi) for the 64x32
// warp tile (4 m-frags x 4 n-frags).
#define COMPUTE_BF_SPLIT(Ahb, Alb, Bhb, Blb) do {                             \
    uint32_t ah[4][4], al[4][4], bh[4][2], bl[4][2];                          \
    _Pragma("unroll")                                                         \
    for (int mi = 0; mi < 4; mi++) {                                          \
        const int m = am0 + mi * 16 + qr;                                     \
        ah[mi][0] = Ahb[qc][m];     ah[mi][1] = Ahb[qc][m + 8];               \
        ah[mi][2] = Ahb[qc + 4][m]; ah[mi][3] = Ahb[qc + 4][m + 8];           \
        al[mi][0] = Alb[qc][m];     al[mi][1] = Alb[qc][m + 8];               \
        al[mi][2] = Alb[qc + 4][m]; al[mi][3] = Alb[qc + 4][m + 8];           \
    }                                                                         \
    _Pragma("unroll")                                                         \
    for (int nj = 0; nj < 4; nj++) {                                          \
        const int n = bn0 + nj * 8 + qr;                                      \
        bh[nj][0] = Bhb[qc][n]; bh[nj][1] = Bhb[qc + 4][n];                   \
        bl[nj][0] = Blb[qc][n]; bl[nj][1] = Blb[qc + 4][n];                   \
    }                                                                         \
    _Pragma("unroll")                                                         \
    for (int mi = 0; mi < 4; mi++)                                            \
        _Pragma("unroll")                                                     \
        for (int nj = 0; nj < 4; nj++) {                                      \
            mma16(acc[mi][nj], ah[mi], bh[nj]);                               \
            mma16(acc[mi][nj], ah[mi], bl[nj]);                               \
            mma16(acc[mi][nj], al[mi], bh[nj]);                               \
        }                                                                     \
} while (0)

// ---------------------------------------------------------------------------
// tf32 staging/compute (k_wc / k_out) — unchanged from R5
// ---------------------------------------------------------------------------
#define STAGE_T(H, v, p) do {                                   \
    const int _r = lrow + (p) * 64;                             \
    H[lcol + 0][_r] = f2tf32((v).x);                            \
    H[lcol + 1][_r] = f2tf32((v).y);                            \
    H[lcol + 2][_r] = f2tf32((v).z);                            \
    H[lcol + 3][_r] = f2tf32((v).w);                            \
} while (0)

#define STAGE_D(H, v, p) do {                                   \
    float4 _cv;                                                 \
    _cv.x = f2tf32((v).x); _cv.y = f2tf32((v).y);               \
    _cv.z = f2tf32((v).z); _cv.w = f2tf32((v).w);               \
    *(float4*)&H[krow + (p) * 8][ncol] = _cv;                   \
} while (0)

#define COMPUTE_TILE(Ahb, Bhb)                                              \
    _Pragma("unroll")                                                       \
    for (int ks = 0; ks < 2; ks++) {                                        \
        const int k0 = ks * 8;                                              \
        float af[4][4], bf[4][2];                                           \
        _Pragma("unroll")                                                   \
        for (int mi = 0; mi < 4; mi++) {                                    \
            const int m = am0 + mi * 16 + qr;                               \
            af[mi][0] = Ahb[k0 + qc][m];     af[mi][1] = Ahb[k0 + qc][m + 8];   \
            af[mi][2] = Ahb[k0 + qc + 4][m]; af[mi][3] = Ahb[k0 + qc + 4][m + 8]; \
        }                                                                   \
        _Pragma("unroll")                                                   \
        for (int nj = 0; nj < 4; nj++) {                                    \
            const int n = bn0 + nj * 8 + qr;                                \
            bf[nj][0] = Bhb[k0 + qc][n]; bf[nj][1] = Bhb[k0 + qc + 4][n];   \
        }                                                                   \
        _Pragma("unroll")                                                   \
        for (int mi = 0; mi < 4; mi++)                                      \
            _Pragma("unroll")                                               \
            for (int nj = 0; nj < 4; nj++)                                  \
                mma8(acc[mi][nj], af[mi], bf[nj]);                          \
    }

#define WARP_IDX_SETUP                                  \
    const int tid = threadIdx.x;                        \
    const int lane = tid & 31, wid = tid >> 5;          \
    const int qr = lane >> 2, qc = lane & 3;            \
    const int am0 = (wid >> 2) * 64;                    \
    const int bn0 = (wid & 3) * 32;                     \
    const int lrow = tid >> 2, lcol = (tid & 3) * 4;    \
    const int skp = (tid & 3) * 2;                      \
    const int krow = tid >> 5, ncol = (tid & 31) * 4;   \
    (void)krow; (void)ncol; (void)lcol; (void)skp;

// Kernel c: c[m] = sum_d dec[m,d] * b_attn[d]
__global__ __launch_bounds__(256)
void k_c(const float* __restrict__ dec, const float* __restrict__ ba)
{
    const int m = blockIdx.x * 8 + (threadIdx.x >> 5);
    const int lane = threadIdx.x & 31;
    float s = 0.0f;
#pragma unroll
    for (int it = 0; it < 4; it++) {
        float4 v = *(const float4*)&dec[(size_t)m * DD + it * 128 + lane * 4];
        float4 w = *(const float4*)&ba[it * 128 + lane * 4];
        s += v.x * w.x + v.y * w.y + v.z * w.z + v.w * w.w;
    }
#pragma unroll
    for (int o = 16; o; o >>= 1) s += __shfl_xor_sync(0xffffffffu, s, o);
    if (lane == 0) g_c[m] = s;
}

// k_P (bf16-split, double-buffered): P[m,e] = sum_d dec[m,d]*W[e,d]
// M=8192, N=1024, K=512
__global__ __launch_bounds__(256)
void k_P(const float* __restrict__ dec, const float* __restrict__ W)
{
    __shared__ uint32_t Ah[2][8][PAD], Al[2][8][PAD];
    __shared__ uint32_t Bh[2][8][PAD], Bl[2][8][PAD];
    WARP_IDX_SETUP
    const int bm = blockIdx.y * 128, bn = blockIdx.x * 128;

    float4 va[2], vb[2];
#pragma unroll
    for (int p = 0; p < 2; p++) {
        va[p] = *(const float4*)&dec[(size_t)(bm + lrow + p * 64) * DD + lcol];
        vb[p] = *(const float4*)&W[(size_t)(bn + lrow + p * 64) * DD + lcol];
    }
    STAGE_BF_SPLIT(Ah[0], Al[0], va[0], 0); STAGE_BF_SPLIT(Ah[0], Al[0], va[1], 1);
    STAGE_BF_SPLIT(Bh[0], Bl[0], vb[0], 0); STAGE_BF_SPLIT(Bh[0], Bl[0], vb[1], 1);
    __syncthreads();

    float acc[4][4][4] = {};
    const int nt = DD / 16;
    for (int t = 0; t < nt; t++) {
        const int cur = t & 1, nxt = cur ^ 1;
        const bool more = (t + 1 < nt);
        if (more) {
            const int k0 = (t + 1) * 16;
#pragma unroll
            for (int p = 0; p < 2; p++) {
                va[p] = *(const float4*)&dec[(size_t)(bm + lrow + p * 64) * DD + k0 + lcol];
                vb[p] = *(const float4*)&W[(size_t)(bn + lrow + p * 64) * DD + k0 + lcol];
            }
        }
        COMPUTE_BF_SPLIT(Ah[cur], Al[cur], Bh[cur], Bl[cur]);
        if (more) {
            STAGE_BF_SPLIT(Ah[nxt], Al[nxt], va[0], 0); STAGE_BF_SPLIT(Ah[nxt], Al[nxt], va[1], 1);
            STAGE_BF_SPLIT(Bh[nxt], Bl[nxt], vb[0], 0); STAGE_BF_SPLIT(Bh[nxt], Bl[nxt], vb[1], 1);
        }
        __syncthreads();
    }
#pragma unroll
    for (int mi = 0; mi < 4; mi++)
#pragma unroll
        for (int nj = 0; nj < 4; nj++) {
            const size_t m = bm + am0 + mi * 16 + qr;
            const int n = bn + bn0 + nj * 8 + qc * 2;
            *(float2*)&g_P[m * EE + n]       = make_float2(acc[mi][nj][0], acc[mi][nj][1]);
            *(float2*)&g_P[(m + 8) * EE + n] = make_float2(acc[mi][nj][2], acc[mi][nj][3]);
        }
}

// k_energy (bf16-split, double-buffered, per batch):
// me[t,s] = mask[s] ? P[t,:].enc[s,:] + c[t] : NEGINF.  M=128, N=128/blk, K=1024
__global__ __launch_bounds__(256)
void k_energy(const float* __restrict__ enc, const int* __restrict__ mask,
              float* __restrict__ me)
{
    __shared__ uint32_t Ah[2][8][PAD], Al[2][8][PAD];
    __shared__ uint32_t Bh[2][8][PAD], Bl[2][8][PAD];
    WARP_IDX_SETUP
    const int b = blockIdx.z;
    const int bn = blockIdx.x * 128;
    const float* A = g_P + (size_t)b * TT * EE;
    const float* Ep = enc + (size_t)b * SS * EE;

    float4 va[2], vb[2];
#pragma unroll
    for (int p = 0; p < 2; p++) {
        va[p] = *(const float4*)&A[(size_t)(lrow + p * 64) * EE + lcol];
        vb[p] = *(const float4*)&Ep[(size_t)(bn + lrow + p * 64) * EE + lcol];
    }
    STAGE_BF_SPLIT(Ah[0], Al[0], va[0], 0); STAGE_BF_SPLIT(Ah[0], Al[0], va[1], 1);
    STAGE_BF_SPLIT(Bh[0], Bl[0], vb[0], 0); STAGE_BF_SPLIT(Bh[0], Bl[0], vb[1], 1);
    __syncthreads();

    float acc[4][4][4] = {};
    const int nt = EE / 16;
    for (int t = 0; t < nt; t++) {
        const int cur = t & 1, nxt = cur ^ 1;
        const bool more = (t + 1 < nt);
        if (more) {
            const int k0 = (t + 1) * 16;
#pragma unroll
            for (int p = 0; p < 2; p++) {
                va[p] = *(const float4*)&A[(size_t)(lrow + p * 64) * EE + k0 + lcol];
                vb[p] = *(const float4*)&Ep[(size_t)(bn + lrow + p * 64) * EE + k0 + lcol];
            }
        }
        COMPUTE_BF_SPLIT(Ah[cur], Al[cur], Bh[cur], Bl[cur]);
        if (more) {
            STAGE_BF_SPLIT(Ah[nxt], Al[nxt], va[0], 0); STAGE_BF_SPLIT(Ah[nxt], Al[nxt], va[1], 1);
            STAGE_BF_SPLIT(Bh[nxt], Bl[nxt], vb[0], 0); STAGE_BF_SPLIT(Bh[nxt], Bl[nxt], vb[1], 1);
        }
        __syncthreads();
    }
#pragma unroll
    for (int mi = 0; mi < 4; mi++) {
        const int t0 = am0 + mi * 16 + qr;
        const float ct0 = g_c[(size_t)b * TT + t0];
        const float ct1 = g_c[(size_t)b * TT + t0 + 8];
#pragma unroll
        for (int nj = 0; nj < 4; nj++) {
            const int s = bn + bn0 + nj * 8 + qc * 2;
            const int mk0 = mask[(size_t)b * SS + s];
            const int mk1 = mask[(size_t)b * SS + s + 1];
            float2 r0, r1;
            r0.x = mk0 ? acc[mi][nj][0] + ct0 : NEGINF;
            r0.y = mk1 ? acc[mi][nj][1] + ct0 : NEGINF;
            r1.x = mk0 ? acc[mi][nj][2] + ct1 : NEGINF;
            r1.y = mk1 ? acc[mi][nj][3] + ct1 : NEGINF;
            *(float2*)&me[((size_t)b * TT + t0) * SS + s]     = r0;
            *(float2*)&me[((size_t)b * TT + t0 + 8) * SS + s] = r1;
        }
    }
}

// Row softmax over S=512, one block (256 thr) per (b,t) row.
__global__ __launch_bounds__(256)
void k_softmax(const float* __restrict__ me, float* __restrict__ attn)
{
    const int row = blockIdx.x;
    const float* x = me + (size_t)row * SS;
    float* y = attn + (size_t)row * SS;
    const int tid = threadIdx.x;
    __shared__ float smax[8];
    __shared__ float ssum[8];

    float v0 = x[tid], v1 = x[tid + 256];
    float m = fmaxf(v0, v1);
#pragma unroll
    for (int o = 16; o; o >>= 1) m = fmaxf(m, __shfl_xor_sync(0xffffffffu, m, o));
    if ((tid & 31) == 0) smax[tid >> 5] = m;
    __syncthreads();
    float M = smax[0];
#pragma unroll
    for (int i = 1; i < 8; i++) M = fmaxf(M, smax[i]);

    float e0 = __expf(v0 - M), e1 = __expf(v1 - M);
    float s = e0 + e1;
#pragma unroll
    for (int o = 16; o; o >>= 1) s += __shfl_xor_sync(0xffffffffu, s, o);
    if ((tid & 31) == 0) ssum[tid >> 5] = s;
    __syncthreads();
    float S = 0.0f;
#pragma unroll
    for (int i = 0; i < 8; i++) S += ssum[i];
    float inv = 1.0f / S;
    y[tid] = e0 * inv;
    y[tid + 256] = e1 * inv;
}

// k_wc (tf32, double-buffered, per batch): wc[t,e] = sum_s attn[t,s]*enc[s,e]
__global__ __launch_bounds__(256)
void k_wc(const float* __restrict__ attn, const float* __restrict__ enc)
{
    __shared__ float Ah[2][16][PAD], Bh[2][16][PAD];
    WARP_IDX_SETUP
    const int b = blockIdx.z;
    const int bn = blockIdx.x * 128;
    const float* A = attn + (size_t)b * TT * SS;
    const float* Ep = enc + (size_t)b * SS * EE;

    float4 va[2], vb[2];
#pragma unroll
    for (int p = 0; p < 2; p++) {
        va[p] = *(const float4*)&A[(size_t)(lrow + p * 64) * SS + lcol];
        vb[p] = *(const float4*)&Ep[(size_t)(krow + p * 8) * EE + bn + ncol];
    }
    STAGE_T(Ah[0], va[0], 0); STAGE_T(Ah[0], va[1], 1);
    STAGE_D(Bh[0], vb[0], 0); STAGE_D(Bh[0], vb[1], 1);
    __syncthreads();

    float acc[4][4][4] = {};
    const int nt = SS / 16;
    for (int t = 0; t < nt; t++) {
        const int cur = t & 1, nxt = cur ^ 1;
        const bool more = (t + 1 < nt);
        if (more) {
            const int k0 = (t + 1) * 16;
#pragma unroll
            for (int p = 0; p < 2; p++) {
                va[p] = *(const float4*)&A[(size_t)(lrow + p * 64) * SS + k0 + lcol];
                vb[p] = *(const float4*)&Ep[(size_t)(k0 + krow + p * 8) * EE + bn + ncol];
            }
        }
        COMPUTE_TILE(Ah[cur], Bh[cur])
        if (more) {
            STAGE_T(Ah[nxt], va[0], 0); STAGE_T(Ah[nxt], va[1], 1);
            STAGE_D(Bh[nxt], vb[0], 0); STAGE_D(Bh[nxt], vb[1], 1);
        }
        __syncthreads();
    }
#pragma unroll
    for (int mi = 0; mi < 4; mi++)
#pragma unroll
        for (int nj = 0; nj < 4; nj++) {
            const size_t m = (size_t)b * TT + am0 + mi * 16 + qr;
            const int n = bn + bn0 + nj * 8 + qc * 2;
            *(float2*)&g_wc[m * EE + n]       = make_float2(acc[mi][nj][0], acc[mi][nj][1]);
            *(float2*)&g_wc[(m + 8) * EE + n] = make_float2(acc[mi][nj][2], acc[mi][nj][3]);
        }
}

// k_out (tf32, double-buffered): ht[m,n] = tanh([wc | dec][m,:] @ W_out[:,n])
__global__ __launch_bounds__(256)
void k_out(const float* __restrict__ dec, const float* __restrict__ Wout,
           float* __restrict__ ht)
{
    __shared__ float Ah[2][16][PAD], Bh[2][16][PAD];
    WARP_IDX_SETUP
    const int bm = blockIdx.y * 128, bn = blockIdx.x * 128;

    float4 va[2], vb[2];
#pragma unroll
    for (int p = 0; p < 2; p++) {
        va[p] = *(const float4*)&g_wc[(size_t)(bm + lrow + p * 64) * EE + lcol];
        vb[p] = *(const float4*)&Wout[(size_t)(krow + p * 8) * DD + bn + ncol];
    }
    STAGE_T(Ah[0], va[0], 0); STAGE_T(Ah[0], va[1], 1);
    STAGE_D(Bh[0], vb[0], 0); STAGE_D(Bh[0], vb[1], 1);
    __syncthreads();

    float acc[4][4][4] = {};
    const int nt = (EE + DD) / 16;
    for (int t = 0; t < nt; t++) {
        const int cur = t & 1, nxt = cur ^ 1;
        const bool more = (t + 1 < nt);
        if (more) {
            const int k0 = (t + 1) * 16;
#pragma unroll
            for (int p = 0; p < 2; p++) {
                if (k0 < EE)
                    va[p] = *(const float4*)&g_wc[(size_t)(bm + lrow + p * 64) * EE + k0 + lcol];
                else
                    va[p] = *(const float4*)&dec[(size_t)(bm + lrow + p * 64) * DD + (k0 - EE) + lcol];
                vb[p] = *(const float4*)&Wout[(size_t)(k0 + krow + p * 8) * DD + bn + ncol];
            }
        }
        COMPUTE_TILE(Ah[cur], Bh[cur])
        if (more) {
            STAGE_T(Ah[nxt], va[0], 0); STAGE_T(Ah[nxt], va[1], 1);
            STAGE_D(Bh[nxt], vb[0], 0); STAGE_D(Bh[nxt], vb[1], 1);
        }
        __syncthreads();
    }
#pragma unroll
    for (int mi = 0; mi < 4; mi++)
#pragma unroll
        for (int nj = 0; nj < 4; nj++) {
            const size_t m = bm + am0 + mi * 16 + qr;
            const int n = bn + bn0 + nj * 8 + qc * 2;
            float2 r0 = make_float2(tanhf(acc[mi][nj][0]), tanhf(acc[mi][nj][1]));
            float2 r1 = make_float2(tanhf(acc[mi][nj][2]), tanhf(acc[mi][nj][3]));
            *(float2*)&ht[m * DD + n]       = r0;
            *(float2*)&ht[(m + 8) * DD + n] = r1;
        }
}

extern "C" void kernel_launch(void* const* d_in, const int* in_sizes, int n_in,
                              void* d_out, int out_size)
{
    const float* dec    = (const float*)d_in[0];  // [B,T,DEC]
    const float* enc    = (const float*)d_in[1];  // [B,S,ENC]
    const int*   mask   = (const int*)d_in[2];    // [B,S]
    const float* W_attn = (const float*)d_in[3];  // [ENC,DEC]
    const float* b_attn = (const float*)d_in[4];  // [DEC]
    const float* W_out  = (const float*)d_in[5];  // [ENC+DEC,DEC]
    float* out = (float*)d_out;

    const size_t n_h    = (size_t)BB * TT * DD;
    const size_t n_attn = (size_t)BB * TT * SS;
    const size_t n_me   = (size_t)BB * TT * SS;

    float* h_tilde = out;
    float* attn;
    float* me;
    if ((size_t)out_size >= n_h + n_attn + n_me) {
        attn = out + n_h;
        me   = out + n_h + n_attn;
    } else {
        void* p;
        cudaGetSymbolAddress(&p, g_attn_scratch); attn = (float*)p;
        cudaGetSymbolAddress(&p, g_me_scratch);   me = (float*)p;
    }

    // 0. c = dec . b_attn
    k_c<<<dim3(BB * TT / 8), 256>>>(dec, b_attn);
    // 1. P = dec @ W_attn^T (bf16-split mma16)    M=8192 N=1024 K=512
    k_P<<<dim3(EE / 128, (BB * TT) / 128), 256>>>(dec, W_attn);
    // 2. masked energies = P @ enc^T (bf16-split) per-batch M=128 N=512 K=1024
    k_energy<<<dim3(SS / 128, 1, BB), 256>>>(enc, mask, me);
    // 3. softmax rows
    k_softmax<<<dim3(BB * TT), 256>>>(me, attn);
    // 4. weighted context (tf32)                  per-batch M=128 N=1024 K=512
    k_wc<<<dim3(EE / 128, 1, BB), 256>>>(attn, enc);
    // 5. h_tilde = tanh([wc, dec] @ W_out)        M=8192 K=1536 N=512
    k_out<<<dim3(DD / 128, (BB * TT) / 128), 256>>>(dec, W_out, h_tilde);
}

// round 9
// speedup vs baseline: 4.0483x; 1.1322x over previous
#include <cuda_runtime.h>
#include <cstdint>

// Problem constants (fixed by dataset)
#define BB 64
#define TT 128
#define SS 512
#define EE 1024
#define DD 512
#define NEGINF (-1.0e10f)
#define PAD 132

// bf16 tile geometry: [128 rows][16 k] bf16, 48B row pitch (32B data + 16B pad)
#define BPITCH 48
#define BTILE  (128 * BPITCH)      // 6144 B
#define BSTG   (4 * BTILE)         // Ah, Al, Bh, Bl per stage = 24576 B
#define SMEM_BF (2 * BSTG)         // 49152 B

// tf32 A tile: [128 m][16 k] fp32, 80B pitch (64B data + 16B pad) = 20 floats
#define APITCH_F 20

// Scratch (allocation-free rule: device globals)
__device__ float g_P[(size_t)BB * TT * EE];
__device__ float g_wc[(size_t)BB * TT * EE];
__device__ float g_c[(size_t)BB * TT];
__device__ float g_attn_scratch[(size_t)BB * TT * SS];
__device__ float g_me_scratch[(size_t)BB * TT * SS];

// ---------------------------------------------------------------------------
// helpers
// ---------------------------------------------------------------------------
__device__ __forceinline__ uint32_t smem_u32(const void* p) {
    uint32_t a;
    asm("{ .reg .u64 t; cvta.to.shared.u64 t, %1; cvt.u32.u64 %0, t; }"
        : "=r"(a) : "l"(p));
    return a;
}

__device__ __forceinline__ float f2tf32(float x) {
    uint32_t u;
    asm("cvt.rna.tf32.f32 %0, %1;" : "=r"(u) : "f"(x));
    return __uint_as_float(u);
}

#define LDSM4(d0, d1, d2, d3, a)                                              \
    asm volatile("ldmatrix.sync.aligned.m8n8.x4.shared.b16 {%0,%1,%2,%3}, [%4];" \
                 : "=r"(d0), "=r"(d1), "=r"(d2), "=r"(d3) : "r"(a))

__device__ __forceinline__ void mma8u(float* d, const uint32_t* a, const float* b) {
    asm volatile(
        "mma.sync.aligned.m16n8k8.row.col.f32.tf32.tf32.f32 "
        "{%0,%1,%2,%3}, {%4,%5,%6,%7}, {%8,%9}, {%0,%1,%2,%3};"
        : "+f"(d[0]), "+f"(d[1]), "+f"(d[2]), "+f"(d[3])
        : "r"(a[0]), "r"(a[1]), "r"(a[2]), "r"(a[3]),
          "r"(__float_as_uint(b[0])), "r"(__float_as_uint(b[1])));
}

__device__ __forceinline__ void mma16(float* d, const uint32_t* a, const uint32_t* b) {
    asm volatile(
        "mma.sync.aligned.m16n8k16.row.col.f32.bf16.bf16.f32 "
        "{%0,%1,%2,%3}, {%4,%5,%6,%7}, {%8,%9}, {%0,%1,%2,%3};"
        : "+f"(d[0]), "+f"(d[1]), "+f"(d[2]), "+f"(d[3])
        : "r"(a[0]), "r"(a[1]), "r"(a[2]), "r"(a[3]), "r"(b[0]), "r"(b[1]));
}

// ---------------------------------------------------------------------------
// bf16 split staging into row-major [row][k] pitch-48B tiles.
// Thread handles rows lrow, lrow+64; k-chunk (tid&3)*4.
// ---------------------------------------------------------------------------
#define STAGE_BF2(hi, lo, v, p) do {                                          \
    const int _r = lrow + (p) * 64;                                           \
    uint32_t _h0, _h1, _l0, _l1;                                              \
    asm("cvt.rn.satfinite.bf16x2.f32 %0, %1, %2;" : "=r"(_h0)                 \
        : "f"((v).y), "f"((v).x));                                            \
    asm("cvt.rn.satfinite.bf16x2.f32 %0, %1, %2;" : "=r"(_h1)                 \
        : "f"((v).w), "f"((v).z));                                            \
    const float _hx = __uint_as_float(_h0 << 16);                             \
    const float _hy = __uint_as_float(_h0 & 0xFFFF0000u);                     \
    const float _hz = __uint_as_float(_h1 << 16);                             \
    const float _hw = __uint_as_float(_h1 & 0xFFFF0000u);                     \
    asm("cvt.rn.satfinite.bf16x2.f32 %0, %1, %2;" : "=r"(_l0)                 \
        : "f"((v).y - _hy), "f"((v).x - _hx));                                \
    asm("cvt.rn.satfinite.bf16x2.f32 %0, %1, %2;" : "=r"(_l1)                 \
        : "f"((v).w - _hw), "f"((v).z - _hz));                                \
    *(uint2*)((hi) + _r * BPITCH + (tid & 3) * 8) = make_uint2(_h0, _h1);     \
    *(uint2*)((lo) + _r * BPITCH + (tid & 3) * 8) = make_uint2(_l0, _l1);     \
} while (0)

// One K16 chunk of bf16 2-term split via ldmatrix. Bases are u32 smem addrs.
#define COMPUTE_BF_LDSM(AHB, ALB, BHB, BLB) do {                              \
    uint32_t ah[4][4], al[4][4], bh[4][2], bl[4][2];                          \
    _Pragma("unroll")                                                         \
    for (int mi = 0; mi < 4; mi++) {                                          \
        const uint32_t _ao = aoff + mi * (16 * BPITCH);                       \
        LDSM4(ah[mi][0], ah[mi][1], ah[mi][2], ah[mi][3], (AHB) + _ao);       \
        LDSM4(al[mi][0], al[mi][1], al[mi][2], al[mi][3], (ALB) + _ao);       \
    }                                                                         \
    _Pragma("unroll")                                                         \
    for (int p = 0; p < 2; p++) {                                             \
        const uint32_t _bo = boff + p * (16 * BPITCH);                        \
        LDSM4(bh[2*p][0], bh[2*p][1], bh[2*p+1][0], bh[2*p+1][1], (BHB) + _bo); \
        LDSM4(bl[2*p][0], bl[2*p][1], bl[2*p+1][0], bl[2*p+1][1], (BLB) + _bo); \
    }                                                                         \
    _Pragma("unroll")                                                         \
    for (int mi = 0; mi < 4; mi++)                                            \
        _Pragma("unroll")                                                     \
        for (int nj = 0; nj < 4; nj++) {                                      \
            mma16(acc[mi][nj], ah[mi], bh[nj]);                               \
            mma16(acc[mi][nj], ah[mi], bl[nj]);                               \
            mma16(acc[mi][nj], al[mi], bh[nj]);                               \
        }                                                                     \
} while (0)

// ---------------------------------------------------------------------------
// tf32 staging/compute for k_wc / k_out.
// A: row-major [m][16k] fp32 pitch-80B, fragments via ldmatrix (b16 view).
// B: [k][n] pitch-PAD floats, scalar LDS (unchanged from R8).
// ---------------------------------------------------------------------------
#define STAGE_A32(dst, v, p) do {                                             \
    const int _r = lrow + (p) * 64;                                           \
    float4 _cv;                                                               \
    _cv.x = f2tf32((v).x); _cv.y = f2tf32((v).y);                             \
    _cv.z = f2tf32((v).z); _cv.w = f2tf32((v).w);                             \
    *(float4*)&(dst)[_r * APITCH_F + (tid & 3) * 4] = _cv;                    \
} while (0)

#define STAGE_D(H, v, p) do {                                   \
    float4 _cv;                                                 \
    _cv.x = f2tf32((v).x); _cv.y = f2tf32((v).y);               \
    _cv.z = f2tf32((v).z); _cv.w = f2tf32((v).w);               \
    *(float4*)&H[krow + (p) * 8][ncol] = _cv;                   \
} while (0)

#define COMPUTE_T32_LDSM(A32B, Bhb)                                           \
    _Pragma("unroll")                                                         \
    for (int ks = 0; ks < 2; ks++) {                                          \
        const int k0 = ks * 8;                                                \
        uint32_t au[4][4];                                                    \
        float bf[4][2];                                                       \
        _Pragma("unroll")                                                     \
        for (int mi = 0; mi < 4; mi++) {                                      \
            const uint32_t _ao = aoff32 + mi * (16 * 80) + ks * 32;           \
            LDSM4(au[mi][0], au[mi][1], au[mi][2], au[mi][3], (A32B) + _ao);  \
        }                                                                     \
        _Pragma("unroll")                                                     \
        for (int nj = 0; nj < 4; nj++) {                                      \
            const int n = bn0 + nj * 8 + qr;                                  \
            bf[nj][0] = Bhb[k0 + qc][n]; bf[nj][1] = Bhb[k0 + qc + 4][n];     \
        }                                                                     \
        _Pragma("unroll")                                                     \
        for (int mi = 0; mi < 4; mi++)                                        \
            _Pragma("unroll")                                                 \
            for (int nj = 0; nj < 4; nj++)                                    \
                mma8u(acc[mi][nj], au[mi], bf[nj]);                           \
    }

#define WARP_IDX_SETUP                                  \
    const int tid = threadIdx.x;                        \
    const int lane = tid & 31, wid = tid >> 5;          \
    const int qr = lane >> 2, qc = lane & 3;            \
    const int am0 = (wid >> 2) * 64;                    \
    const int bn0 = (wid & 3) * 32;                     \
    const int lrow = tid >> 2, lcol = (tid & 3) * 4;    \
    const int krow = tid >> 5, ncol = (tid & 31) * 4;   \
    (void)qr; (void)qc; (void)krow; (void)ncol; (void)lcol;

// ldmatrix lane-address components (row within group + k-halve offsets)
#define LDSM_A_IDX                                                            \
    const int a_row = ((lane >> 3) & 1) * 8 + (lane & 7);                     \
    const int a_kh  = ((lane >> 4) & 1) * 16;
#define LDSM_B_IDX                                                            \
    const int b_row = ((lane >> 4) & 1) * 8 + (lane & 7);                     \
    const int b_kh  = ((lane >> 3) & 1) * 16;

// Kernel c: c[m] = sum_d dec[m,d] * b_attn[d]
__global__ __launch_bounds__(256)
void k_c(const float* __restrict__ dec, const float* __restrict__ ba)
{
    const int m = blockIdx.x * 8 + (threadIdx.x >> 5);
    const int lane = threadIdx.x & 31;
    float s = 0.0f;
#pragma unroll
    for (int it = 0; it < 4; it++) {
        float4 v = *(const float4*)&dec[(size_t)m * DD + it * 128 + lane * 4];
        float4 w = *(const float4*)&ba[it * 128 + lane * 4];
        s += v.x * w.x + v.y * w.y + v.z * w.z + v.w * w.w;
    }
#pragma unroll
    for (int o = 16; o; o >>= 1) s += __shfl_xor_sync(0xffffffffu, s, o);
    if (lane == 0) g_c[m] = s;
}

// k_P (bf16-split + ldmatrix): P[m,e] = sum_d dec[m,d]*W[e,d]  M=8192,N=1024,K=512
__global__ __launch_bounds__(256)
void k_P(const float* __restrict__ dec, const float* __restrict__ W)
{
    extern __shared__ char smx[];
    WARP_IDX_SETUP
    LDSM_A_IDX
    LDSM_B_IDX
    const int bm = blockIdx.y * 128, bn = blockIdx.x * 128;
    const uint32_t sb = smem_u32(smx);
    const uint32_t aoff = (am0 + a_row) * BPITCH + a_kh;
    const uint32_t boff = (bn0 + b_row) * BPITCH + b_kh;

    float4 va[2], vb[2];
#pragma unroll
    for (int p = 0; p < 2; p++) {
        va[p] = *(const float4*)&dec[(size_t)(bm + lrow + p * 64) * DD + lcol];
        vb[p] = *(const float4*)&W[(size_t)(bn + lrow + p * 64) * DD + lcol];
    }
    {
        char* b0 = smx;
        STAGE_BF2(b0, b0 + BTILE, va[0], 0); STAGE_BF2(b0, b0 + BTILE, va[1], 1);
        STAGE_BF2(b0 + 2*BTILE, b0 + 3*BTILE, vb[0], 0);
        STAGE_BF2(b0 + 2*BTILE, b0 + 3*BTILE, vb[1], 1);
    }
    __syncthreads();

    float acc[4][4][4] = {};
    const int nt = DD / 16;
    for (int t = 0; t < nt; t++) {
        const int cur = t & 1, nxt = cur ^ 1;
        const bool more = (t + 1 < nt);
        if (more) {
            const int k0 = (t + 1) * 16;
#pragma unroll
            for (int p = 0; p < 2; p++) {
                va[p] = *(const float4*)&dec[(size_t)(bm + lrow + p * 64) * DD + k0 + lcol];
                vb[p] = *(const float4*)&W[(size_t)(bn + lrow + p * 64) * DD + k0 + lcol];
            }
        }
        {
            const uint32_t s0 = sb + cur * BSTG;
            COMPUTE_BF_LDSM(s0, s0 + BTILE, s0 + 2*BTILE, s0 + 3*BTILE);
        }
        if (more) {
            char* b1 = smx + nxt * BSTG;
            STAGE_BF2(b1, b1 + BTILE, va[0], 0); STAGE_BF2(b1, b1 + BTILE, va[1], 1);
            STAGE_BF2(b1 + 2*BTILE, b1 + 3*BTILE, vb[0], 0);
            STAGE_BF2(b1 + 2*BTILE, b1 + 3*BTILE, vb[1], 1);
        }
        __syncthreads();
    }
#pragma unroll
    for (int mi = 0; mi < 4; mi++)
#pragma unroll
        for (int nj = 0; nj < 4; nj++) {
            const size_t m = bm + am0 + mi * 16 + qr;
            const int n = bn + bn0 + nj * 8 + qc * 2;
            *(float2*)&g_P[m * EE + n]       = make_float2(acc[mi][nj][0], acc[mi][nj][1]);
            *(float2*)&g_P[(m + 8) * EE + n] = make_float2(acc[mi][nj][2], acc[mi][nj][3]);
        }
}

// k_energy (bf16-split + ldmatrix, per batch): M=128, N=128/blk, K=1024
__global__ __launch_bounds__(256)
void k_energy(const float* __restrict__ enc, const int* __restrict__ mask,
              float* __restrict__ me)
{
    extern __shared__ char smx[];
    WARP_IDX_SETUP
    LDSM_A_IDX
    LDSM_B_IDX
    const int b = blockIdx.z;
    const int bn = blockIdx.x * 128;
    const float* A = g_P + (size_t)b * TT * EE;
    const float* Ep = enc + (size_t)b * SS * EE;
    const uint32_t sb = smem_u32(smx);
    const uint32_t aoff = (am0 + a_row) * BPITCH + a_kh;
    const uint32_t boff = (bn0 + b_row) * BPITCH + b_kh;

    float4 va[2], vb[2];
#pragma unroll
    for (int p = 0; p < 2; p++) {
        va[p] = *(const float4*)&A[(size_t)(lrow + p * 64) * EE + lcol];
        vb[p] = *(const float4*)&Ep[(size_t)(bn + lrow + p * 64) * EE + lcol];
    }
    {
        char* b0 = smx;
        STAGE_BF2(b0, b0 + BTILE, va[0], 0); STAGE_BF2(b0, b0 + BTILE, va[1], 1);
        STAGE_BF2(b0 + 2*BTILE, b0 + 3*BTILE, vb[0], 0);
        STAGE_BF2(b0 + 2*BTILE, b0 + 3*BTILE, vb[1], 1);
    }
    __syncthreads();

    float acc[4][4][4] = {};
    const int nt = EE / 16;
    for (int t = 0; t < nt; t++) {
        const int cur = t & 1, nxt = cur ^ 1;
        const bool more = (t + 1 < nt);
        if (more) {
            const int k0 = (t + 1) * 16;
#pragma unroll
            for (int p = 0; p < 2; p++) {
                va[p] = *(const float4*)&A[(size_t)(lrow + p * 64) * EE + k0 + lcol];
                vb[p] = *(const float4*)&Ep[(size_t)(bn + lrow + p * 64) * EE + k0 + lcol];
            }
        }
        {
            const uint32_t s0 = sb + cur * BSTG;
            COMPUTE_BF_LDSM(s0, s0 + BTILE, s0 + 2*BTILE, s0 + 3*BTILE);
        }
        if (more) {
            char* b1 = smx + nxt * BSTG;
            STAGE_BF2(b1, b1 + BTILE, va[0], 0); STAGE_BF2(b1, b1 + BTILE, va[1], 1);
            STAGE_BF2(b1 + 2*BTILE, b1 + 3*BTILE, vb[0], 0);
            STAGE_BF2(b1 + 2*BTILE, b1 + 3*BTILE, vb[1], 1);
        }
        __syncthreads();
    }
#pragma unroll
    for (int mi = 0; mi < 4; mi++) {
        const int t0 = am0 + mi * 16 + qr;
        const float ct0 = g_c[(size_t)b * TT + t0];
        const float ct1 = g_c[(size_t)b * TT + t0 + 8];
#pragma unroll
        for (int nj = 0; nj < 4; nj++) {
            const int s = bn + bn0 + nj * 8 + qc * 2;
            const int mk0 = mask[(size_t)b * SS + s];
            const int mk1 = mask[(size_t)b * SS + s + 1];
            float2 r0, r1;
            r0.x = mk0 ? acc[mi][nj][0] + ct0 : NEGINF;
            r0.y = mk1 ? acc[mi][nj][1] + ct0 : NEGINF;
            r1.x = mk0 ? acc[mi][nj][2] + ct1 : NEGINF;
            r1.y = mk1 ? acc[mi][nj][3] + ct1 : NEGINF;
            *(float2*)&me[((size_t)b * TT + t0) * SS + s]     = r0;
            *(float2*)&me[((size_t)b * TT + t0 + 8) * SS + s] = r1;
        }
    }
}

// Row softmax over S=512, one block (256 thr) per (b,t) row.
__global__ __launch_bounds__(256)
void k_softmax(const float* __restrict__ me, float* __restrict__ attn)
{
    const int row = blockIdx.x;
    const float* x = me + (size_t)row * SS;
    float* y = attn + (size_t)row * SS;
    const int tid = threadIdx.x;
    __shared__ float smax[8];
    __shared__ float ssum[8];

    float v0 = x[tid], v1 = x[tid + 256];
    float m = fmaxf(v0, v1);
#pragma unroll
    for (int o = 16; o; o >>= 1) m = fmaxf(m, __shfl_xor_sync(0xffffffffu, m, o));
    if ((tid & 31) == 0) smax[tid >> 5] = m;
    __syncthreads();
    float M = smax[0];
#pragma unroll
    for (int i = 1; i < 8; i++) M = fmaxf(M, smax[i]);

    float e0 = __expf(v0 - M), e1 = __expf(v1 - M);
    float s = e0 + e1;
#pragma unroll
    for (int o = 16; o; o >>= 1) s += __shfl_xor_sync(0xffffffffu, s, o);
    if ((tid & 31) == 0) ssum[tid >> 5] = s;
    __syncthreads();
    float S = 0.0f;
#pragma unroll
    for (int i = 0; i < 8; i++) S += ssum[i];
    float inv = 1.0f / S;
    y[tid] = e0 * inv;
    y[tid + 256] = e1 * inv;
}

// k_wc (tf32 + A-ldmatrix, per batch): wc[t,e] = sum_s attn[t,s]*enc[s,e]
__global__ __launch_bounds__(256)
void k_wc(const float* __restrict__ attn, const float* __restrict__ enc)
{
    __shared__ float A32[2][128 * APITCH_F];
    __shared__ float Bh[2][16][PAD];
    WARP_IDX_SETUP
    LDSM_A_IDX
    const int b = blockIdx.z;
    const int bn = blockIdx.x * 128;
    const float* A = attn + (size_t)b * TT * SS;
    const float* Ep = enc + (size_t)b * SS * EE;
    const uint32_t a32b[2] = { smem_u32(A32[0]), smem_u32(A32[1]) };
    const uint32_t aoff32 = (am0 + a_row) * 80 + a_kh;

    float4 va[2], vb[2];
#pragma unroll
    for (int p = 0; p < 2; p++) {
        va[p] = *(const float4*)&A[(size_t)(lrow + p * 64) * SS + lcol];
        vb[p] = *(const float4*)&Ep[(size_t)(krow + p * 8) * EE + bn + ncol];
    }
    STAGE_A32(A32[0], va[0], 0); STAGE_A32(A32[0], va[1], 1);
    STAGE_D(Bh[0], vb[0], 0); STAGE_D(Bh[0], vb[1], 1);
    __syncthreads();

    float acc[4][4][4] = {};
    const int nt = SS / 16;
    for (int t = 0; t < nt; t++) {
        const int cur = t & 1, nxt = cur ^ 1;
        const bool more = (t + 1 < nt);
        if (more) {
            const int k0 = (t + 1) * 16;
#pragma unroll
            for (int p = 0; p < 2; p++) {
                va[p] = *(const float4*)&A[(size_t)(lrow + p * 64) * SS + k0 + lcol];
                vb[p] = *(const float4*)&Ep[(size_t)(k0 + krow + p * 8) * EE + bn + ncol];
            }
        }
        COMPUTE_T32_LDSM(a32b[cur], Bh[cur])
        if (more) {
            STAGE_A32(A32[nxt], va[0], 0); STAGE_A32(A32[nxt], va[1], 1);
            STAGE_D(Bh[nxt], vb[0], 0); STAGE_D(Bh[nxt], vb[1], 1);
        }
        __syncthreads();
    }
#pragma unroll
    for (int mi = 0; mi < 4; mi++)
#pragma unroll
        for (int nj = 0; nj < 4; nj++) {
            const size_t m = (size_t)b * TT + am0 + mi * 16 + qr;
            const int n = bn + bn0 + nj * 8 + qc * 2;
            *(float2*)&g_wc[m * EE + n]       = make_float2(acc[mi][nj][0], acc[mi][nj][1]);
            *(float2*)&g_wc[(m + 8) * EE + n] = make_float2(acc[mi][nj][2], acc[mi][nj][3]);
        }
}

// k_out (tf32 + A-ldmatrix): ht[m,n] = tanh([wc | dec][m,:] @ W_out[:,n])
__global__ __launch_bounds__(256)
void k_out(const float* __restrict__ dec, const float* __restrict__ Wout,
           float* __restrict__ ht)
{
    __shared__ float A32[2][128 * APITCH_F];
    __shared__ float Bh[2][16][PAD];
    WARP_IDX_SETUP
    LDSM_A_IDX
    const int bm = blockIdx.y * 128, bn = blockIdx.x * 128;
    const uint32_t a32b[2] = { smem_u32(A32[0]), smem_u32(A32[1]) };
    const uint32_t aoff32 = (am0 + a_row) * 80 + a_kh;

    float4 va[2], vb[2];
#pragma unroll
    for (int p = 0; p < 2; p++) {
        va[p] = *(const float4*)&g_wc[(size_t)(bm + lrow + p * 64) * EE + lcol];
        vb[p] = *(const float4*)&Wout[(size_t)(krow + p * 8) * DD + bn + ncol];
    }
    STAGE_A32(A32[0], va[0], 0); STAGE_A32(A32[0], va[1], 1);
    STAGE_D(Bh[0], vb[0], 0); STAGE_D(Bh[0], vb[1], 1);
    __syncthreads();

    float acc[4][4][4] = {};
    const int nt = (EE + DD) / 16;
    for (int t = 0; t < nt; t++) {
        const int cur = t & 1, nxt = cur ^ 1;
        const bool more = (t + 1 < nt);
        if (more) {
            const int k0 = (t + 1) * 16;
#pragma unroll
            for (int p = 0; p < 2; p++) {
                if (k0 < EE)
                    va[p] = *(const float4*)&g_wc[(size_t)(bm + lrow + p * 64) * EE + k0 + lcol];
                else
                    va[p] = *(const float4*)&dec[(size_t)(bm + lrow + p * 64) * DD + (k0 - EE) + lcol];
                vb[p] = *(const float4*)&Wout[(size_t)(k0 + krow + p * 8) * DD + bn + ncol];
            }
        }
        COMPUTE_T32_LDSM(a32b[cur], Bh[cur])
        if (more) {
            STAGE_A32(A32[nxt], va[0], 0); STAGE_A32(A32[nxt], va[1], 1);
            STAGE_D(Bh[nxt], vb[0], 0); STAGE_D(Bh[nxt], vb[1], 1);
        }
        __syncthreads();
    }
#pragma unroll
    for (int mi = 0; mi < 4; mi++)
#pragma unroll
        for (int nj = 0; nj < 4; nj++) {
            const size_t m = bm + am0 + mi * 16 + qr;
            const int n = bn + bn0 + nj * 8 + qc * 2;
            float2 r0 = make_float2(tanhf(acc[mi][nj][0]), tanhf(acc[mi][nj][1]));
            float2 r1 = make_float2(tanhf(acc[mi][nj][2]), tanhf(acc[mi][nj][3]));
            *(float2*)&ht[m * DD + n]       = r0;
            *(float2*)&ht[(m + 8) * DD + n] = r1;
        }
}

extern "C" void kernel_launch(void* const* d_in, const int* in_sizes, int n_in,
                              void* d_out, int out_size)
{
    const float* dec    = (const float*)d_in[0];
    const float* enc    = (const float*)d_in[1];
    const int*   mask   = (const int*)d_in[2];
    const float* W_attn = (const float*)d_in[3];
    const float* b_attn = (const float*)d_in[4];
    const float* W_out  = (const float*)d_in[5];
    float* out = (float*)d_out;

    const size_t n_h    = (size_t)BB * TT * DD;
    const size_t n_attn = (size_t)BB * TT * SS;
    const size_t n_me   = (size_t)BB * TT * SS;

    float* h_tilde = out;
    float* attn;
    float* me;
    if ((size_t)out_size >= n_h + n_attn + n_me) {
        attn = out + n_h;
        me   = out + n_h + n_attn;
    } else {
        void* p;
        cudaGetSymbolAddress(&p, g_attn_scratch); attn = (float*)p;
        cudaGetSymbolAddress(&p, g_me_scratch);   me = (float*)p;
    }

    cudaFuncSetAttribute(k_P, cudaFuncAttributeMaxDynamicSharedMemorySize, SMEM_BF);
    cudaFuncSetAttribute(k_energy, cudaFuncAttributeMaxDynamicSharedMemorySize, SMEM_BF);

    // 0. c = dec . b_attn
    k_c<<<dim3(BB * TT / 8), 256>>>(dec, b_attn);
    // 1. P = dec @ W_attn^T (bf16-split + ldmatrix)   M=8192 N=1024 K=512
    k_P<<<dim3(EE / 128, (BB * TT) / 128), 256, SMEM_BF>>>(dec, W_attn);
    // 2. masked energies (bf16-split + ldmatrix)      per-batch M=128 N=512 K=1024
    k_energy<<<dim3(SS / 128, 1, BB), 256, SMEM_BF>>>(enc, mask, me);
    // 3. softmax rows
    k_softmax<<<dim3(BB * TT), 256>>>(me, attn);
    // 4. weighted context (tf32 + A-ldmatrix)         per-batch M=128 N=1024 K=512
    k_wc<<<dim3(EE / 128, 1, BB), 256>>>(attn, enc);
    // 5. h_tilde = tanh([wc, dec] @ W_out)            M=8192 K=1536 N=512
    k_out<<<dim3(DD / 128, (BB * TT) / 128), 256>>>(dec, W_out, h_tilde);
}